// round 1
// baseline (speedup 1.0000x reference)
#include <cuda_runtime.h>
#include <math.h>

#define Ntok 4096
#define Bb   8
#define Cc   512
#define Hh   8
#define Dd   64
#define BH   64          // B*H
#define EPSf 1e-6f

// ---------------- scratch (static device arrays; no allocation) ----------------
__device__ float g_q[BH * Ntok * Dd];      // (B,H,N,D) sigmoid(q proj)   64 MB
__device__ float g_k[BH * Ntok * Dd];      // (B,H,N,D) sigmoid(k proj)   64 MB
__device__ float g_v[BH * Ntok * Dd];      // (B,H,N,D) v proj            64 MB
__device__ float g_opre[Bb * Ntok * Cc];   // (B,N,C) pre-output          64 MB
__device__ float g_ksum[BH * Dd], g_qsum[BH * Dd];
__device__ float g_kso[BH * Dd],  g_qsi[BH * Dd];
__device__ float g_si[BH * Ntok], g_so[BH * Ntok];
__device__ float g_sa[BH * Ntok], g_cs[BH * Ntok], g_comp[BH * Ntok];
__device__ float g_kpart[8 * BH * Dd], g_qpart[8 * BH * Dd];
__device__ float g_kv[BH * Dd * Dd];
__device__ float g_kvpart[8 * BH * Dd * Dd];

// ---------------- 128x128x8 register-blocked SGEMM ----------------
// M = 32768 rows, N = 512 cols, K = 512.
// MODE 0: q proj  (sigmoid epilogue, store to g_q in (B,H,N,D))
// MODE 1: k proj  (sigmoid epilogue, store to g_k)
// MODE 2: v proj  (plain,            store to g_v)
// MODE 3: output  (A = g_opre, +bias +residual(query), store to d_out (N,B,C))
template <int MODE>
__global__ void __launch_bounds__(256) sgemm_k(
    const float* __restrict__ A, const float* __restrict__ W,
    const float* __restrict__ bias, const float* __restrict__ resid,
    float* __restrict__ out)
{
    __shared__ float As[8][128];
    __shared__ float Bs[8][128];
    const int tid = threadIdx.x;
    const int bm = blockIdx.y * 128;
    const int bn = blockIdx.x * 128;

    const float* Abase = (MODE == 3) ? (const float*)g_opre : A;
    const float* Ap = Abase + (size_t)(bm + (tid >> 1)) * Cc + ((tid & 1) << 2);
    const float* Wp = W + (size_t)(tid >> 5) * Cc + bn + ((tid & 31) << 2);

    const int tx = tid & 15;   // 16 col groups of 8
    const int ty = tid >> 4;   // 16 row groups of 8

    float acc[8][8];
#pragma unroll
    for (int i = 0; i < 8; i++)
#pragma unroll
        for (int j = 0; j < 8; j++) acc[i][j] = 0.f;

    const int am = tid >> 1, ak = (tid & 1) << 2;
    for (int k0 = 0; k0 < Cc; k0 += 8) {
        float4 a4 = *(const float4*)(Ap + k0);
        float4 b4 = *(const float4*)(Wp + (size_t)k0 * Cc);
        As[ak + 0][am] = a4.x; As[ak + 1][am] = a4.y;
        As[ak + 2][am] = a4.z; As[ak + 3][am] = a4.w;
        *(float4*)&Bs[tid >> 5][(tid & 31) << 2] = b4;
        __syncthreads();
#pragma unroll
        for (int kk = 0; kk < 8; kk++) {
            float4 a0 = *(const float4*)&As[kk][ty * 8];
            float4 a1 = *(const float4*)&As[kk][ty * 8 + 4];
            float4 b0 = *(const float4*)&Bs[kk][tx * 8];
            float4 b1 = *(const float4*)&Bs[kk][tx * 8 + 4];
            float ar[8] = {a0.x, a0.y, a0.z, a0.w, a1.x, a1.y, a1.z, a1.w};
            float br[8] = {b0.x, b0.y, b0.z, b0.w, b1.x, b1.y, b1.z, b1.w};
#pragma unroll
            for (int i = 0; i < 8; i++)
#pragma unroll
                for (int j = 0; j < 8; j++)
                    acc[i][j] = fmaf(ar[i], br[j], acc[i][j]);
        }
        __syncthreads();
    }

    float* dst = (MODE == 0) ? g_q : (MODE == 1) ? g_k : g_v;
#pragma unroll
    for (int i = 0; i < 8; i++) {
        const int r = bm + ty * 8 + i;
#pragma unroll
        for (int j = 0; j < 8; j++) {
            const int c = bn + tx * 8 + j;
            float v = acc[i][j] + bias[c];
            if (MODE == 0 || MODE == 1) v = 1.f / (1.f + expf(-v));
            if (MODE <= 2) {
                // r = n*B + b ; c = h*64 + d  -> (B,H,N,D)
                const int n = r >> 3, b = r & 7;
                const int h = c >> 6, d = c & 63;
                dst[(size_t)(((b << 3) | h) * Ntok + n) * Dd + d] = v;
            } else {
                // r = b*N + n ; out is (N,B,C); residual add
                const int b = r >> 12, n = r & 4095;
                const size_t oi = (size_t)((n << 3) | b) * Cc + c;
                out[oi] = v + resid[oi];
            }
        }
    }
}

// ---------------- column sums over s (optionally weighted) ----------------
// grid (8 chunks, 64 bh), block 256. Writes deterministic partials.
__global__ void k_colsum(int weighted)
{
    const int bh = blockIdx.y, chunk = blockIdx.x;
    const int d = threadIdx.x & 63, p = threadIdx.x >> 6;
    const float* kb = g_k + (size_t)bh * Ntok * Dd;
    const float* qb = g_q + (size_t)bh * Ntok * Dd;
    float ak = 0.f, aq = 0.f;
    const int s0 = chunk * 512;
    for (int s = s0 + p; s < s0 + 512; s += 4) {
        float wk = 1.f, wq = 1.f;
        if (weighted) { wk = g_so[bh * Ntok + s]; wq = g_si[bh * Ntok + s]; }
        ak += kb[(size_t)s * Dd + d] * wk;
        aq += qb[(size_t)s * Dd + d] * wq;
    }
    __shared__ float sk[4][64], sq[4][64];
    sk[p][d] = ak; sq[p][d] = aq;
    __syncthreads();
    if (p == 0) {
        g_kpart[(chunk * BH + bh) * Dd + d] = sk[0][d] + sk[1][d] + sk[2][d] + sk[3][d];
        g_qpart[(chunk * BH + bh) * Dd + d] = sq[0][d] + sq[1][d] + sq[2][d] + sq[3][d];
    }
}

__global__ void k_red(int mode)
{
    const int i = blockIdx.x * blockDim.x + threadIdx.x;
    if (i >= BH * Dd) return;
    float sk = 0.f, sq = 0.f;
#pragma unroll
    for (int c = 0; c < 8; c++) {
        sk += g_kpart[c * BH * Dd + i];
        sq += g_qpart[c * BH * Dd + i];
    }
    if (mode == 0) { g_ksum[i] = sk; g_qsum[i] = sq; }
    else           { g_kso[i]  = sk; g_qsi[i]  = sq; }
}

// ---------------- per-row reciprocal dots (sink_incoming / source_outgoing) ----------------
// one warp per row; grid 32768 x 256
__global__ void k_rownorm()
{
    const int w = (blockIdx.x * blockDim.x + threadIdx.x) >> 5; // row id 0..262143
    const int lane = threadIdx.x & 31;
    const int bh = w >> 12;
    const float* qr  = g_q + (size_t)w * Dd;
    const float* kr  = g_k + (size_t)w * Dd;
    const float* ksv = g_ksum + bh * Dd;
    const float* qsv = g_qsum + bh * Dd;
    float s1 = (qr[lane] + EPSf) * (ksv[lane] + EPSf)
             + (qr[lane + 32] + EPSf) * (ksv[lane + 32] + EPSf);
    float s2 = (kr[lane] + EPSf) * (qsv[lane] + EPSf)
             + (kr[lane + 32] + EPSf) * (qsv[lane + 32] + EPSf);
#pragma unroll
    for (int o = 16; o > 0; o >>= 1) {
        s1 += __shfl_xor_sync(0xffffffffu, s1, o);
        s2 += __shfl_xor_sync(0xffffffffu, s2, o);
    }
    if (lane == 0) {
        g_si[w] = 1.f / (s1 + EPSf);
        g_so[w] = 1.f / (s2 + EPSf);
    }
}

// ---------------- conserved sink/source -> sink_allocation, clipped source ----------------
__global__ void k_conserved()
{
    const int w = (blockIdx.x * blockDim.x + threadIdx.x) >> 5;
    const int lane = threadIdx.x & 31;
    const int bh = w >> 12;
    const float* qr  = g_q + (size_t)w * Dd;
    const float* kr  = g_k + (size_t)w * Dd;
    const float* kso = g_kso + bh * Dd;
    const float* qsi = g_qsi + bh * Dd;
    float s1 = (qr[lane] + EPSf) * (kso[lane] + EPSf)
             + (qr[lane + 32] + EPSf) * (kso[lane + 32] + EPSf);
    float s2 = (kr[lane] + EPSf) * (qsi[lane] + EPSf)
             + (kr[lane + 32] + EPSf) * (qsi[lane + 32] + EPSf);
#pragma unroll
    for (int o = 16; o > 0; o >>= 1) {
        s1 += __shfl_xor_sync(0xffffffffu, s1, o);
        s2 += __shfl_xor_sync(0xffffffffu, s2, o);
    }
    if (lane == 0) {
        float cs_sink = s1 + EPSf;                       // * (N/hw) == 1
        g_sa[w] = 1.f / (1.f + expf(-cs_sink));
        float cs_src = s2 + EPSf;
        g_cs[w] = fminf(1.f, fmaxf(-1.f, cs_src));
    }
}

// ---------------- softmax over s (per bh), scaled by C ----------------
__global__ void k_softmax(const float* __restrict__ tptr)
{
    const int bh = blockIdx.x, t = threadIdx.x;
    const float* cs = g_cs + bh * Ntok;
    const float invT = 1.f / tptr[0];
    float v[16];
    float lmax = -3.4e38f;
#pragma unroll
    for (int i = 0; i < 16; i++) {
        v[i] = cs[t + (i << 8)];
        lmax = fmaxf(lmax, v[i]);
    }
    __shared__ float red[256];
    red[t] = lmax; __syncthreads();
    for (int o = 128; o > 0; o >>= 1) { if (t < o) red[t] = fmaxf(red[t], red[t + o]); __syncthreads(); }
    const float mx = red[0];
    __syncthreads();
    float lsum = 0.f;
#pragma unroll
    for (int i = 0; i < 16; i++) { v[i] = expf((v[i] - mx) * invT); lsum += v[i]; }
    red[t] = lsum; __syncthreads();
    for (int o = 128; o > 0; o >>= 1) { if (t < o) red[t] += red[t + o]; __syncthreads(); }
    const float scale = (float)Cc / red[0];
#pragma unroll
    for (int i = 0; i < 16; i++) g_comp[bh * Ntok + t + (i << 8)] = v[i] * scale;
}

// ---------------- kv[d][e] = sum_s k[s,d] * v[s,e] * comp[s] (partials per chunk) ----------------
__global__ void __launch_bounds__(256) k_kv()
{
    const int bh = blockIdx.y, chunk = blockIdx.x;
    __shared__ float ks[32][64];
    __shared__ float ws[32][64];
    const int tid = threadIdx.x;
    const int lr = tid >> 3;          // 0..31
    const int lc = (tid & 7) << 3;    // 0,8,...,56
    const size_t base = (size_t)bh * Ntok * Dd;
    const int d0 = (tid & 15) << 2, e0 = (tid >> 4) << 2;
    float acc[4][4] = {};
    for (int s0 = chunk * 512; s0 < chunk * 512 + 512; s0 += 32) {
        const int s = s0 + lr;
        const float cmp = g_comp[bh * Ntok + s];
        float4 ka = *(const float4*)(g_k + base + (size_t)s * Dd + lc);
        float4 kb = *(const float4*)(g_k + base + (size_t)s * Dd + lc + 4);
        float4 va = *(const float4*)(g_v + base + (size_t)s * Dd + lc);
        float4 vb = *(const float4*)(g_v + base + (size_t)s * Dd + lc + 4);
        *(float4*)&ks[lr][lc]     = ka;
        *(float4*)&ks[lr][lc + 4] = kb;
        va.x *= cmp; va.y *= cmp; va.z *= cmp; va.w *= cmp;
        vb.x *= cmp; vb.y *= cmp; vb.z *= cmp; vb.w *= cmp;
        *(float4*)&ws[lr][lc]     = va;
        *(float4*)&ws[lr][lc + 4] = vb;
        __syncthreads();
#pragma unroll
        for (int ss = 0; ss < 32; ss++) {
            float4 kf = *(const float4*)&ks[ss][d0];
            float4 wf = *(const float4*)&ws[ss][e0];
            float kr[4] = {kf.x, kf.y, kf.z, kf.w};
            float wr[4] = {wf.x, wf.y, wf.z, wf.w};
#pragma unroll
            for (int i = 0; i < 4; i++)
#pragma unroll
                for (int j = 0; j < 4; j++)
                    acc[i][j] = fmaf(kr[i], wr[j], acc[i][j]);
        }
        __syncthreads();
    }
    float* dst = g_kvpart + ((size_t)chunk * BH + bh) * Dd * Dd;
#pragma unroll
    for (int i = 0; i < 4; i++)
#pragma unroll
        for (int j = 0; j < 4; j++)
            dst[(d0 + i) * Dd + e0 + j] = acc[i][j];
}

__global__ void k_kvred()
{
    const int i = blockIdx.x * blockDim.x + threadIdx.x;
    if (i >= BH * Dd * Dd) return;
    float s = 0.f;
#pragma unroll
    for (int c = 0; c < 8; c++) s += g_kvpart[(size_t)c * BH * Dd * Dd + i];
    g_kv[i] = s;
}

// ---------------- out_update = (q @ kv) * si * sa -> scrambled (B,N,C) layout ----------------
__global__ void __launch_bounds__(256) k_outupd()
{
    const int bh = blockIdx.y, nt = blockIdx.x;   // 64 n-tiles of 64 rows
    const int b = bh >> 3, h = bh & 7;
    __shared__ float kvs[64][64];
    __shared__ float qsT[64][68];   // transposed q tile (68 keeps 16B row alignment)
    const int tid = threadIdx.x;

    const float4* kvsrc = (const float4*)(g_kv + (size_t)bh * (Dd * Dd));
    for (int i = tid; i < 1024; i += 256) ((float4*)kvs)[i] = kvsrc[i];

    const int lr = tid >> 3;            // 0..31
    const int lc = (tid & 7) << 3;      // 0..56
    const float* qb = g_q + (size_t)bh * Ntok * Dd + (size_t)(nt * 64) * Dd;
#pragma unroll
    for (int rr = lr; rr < 64; rr += 32) {
        float4 q0 = *(const float4*)(qb + rr * Dd + lc);
        float4 q1 = *(const float4*)(qb + rr * Dd + lc + 4);
        qsT[lc + 0][rr] = q0.x; qsT[lc + 1][rr] = q0.y;
        qsT[lc + 2][rr] = q0.z; qsT[lc + 3][rr] = q0.w;
        qsT[lc + 4][rr] = q1.x; qsT[lc + 5][rr] = q1.y;
        qsT[lc + 6][rr] = q1.z; qsT[lc + 7][rr] = q1.w;
    }
    __syncthreads();

    const int n0 = (tid & 15) << 2, e0 = (tid >> 4) << 2;
    float acc[4][4] = {};
#pragma unroll
    for (int d = 0; d < 64; d++) {
        float4 qa = *(const float4*)&qsT[d][n0];
        float4 kf = *(const float4*)&kvs[d][e0];
        float qr[4] = {qa.x, qa.y, qa.z, qa.w};
        float kr[4] = {kf.x, kf.y, kf.z, kf.w};
#pragma unroll
        for (int i = 0; i < 4; i++)
#pragma unroll
            for (int j = 0; j < 4; j++)
                acc[i][j] = fmaf(qr[i], kr[j], acc[i][j]);
    }

#pragma unroll
    for (int i = 0; i < 4; i++) {
        const int n = nt * 64 + n0 + i;
        const float scale = g_si[bh * Ntok + n] * g_sa[bh * Ntok + n];
        const int np = (h << 9) | (n >> 3);        // n' = h*512 + n/8
        const int cbase = (n & 7) << 6;            // c' base = (n%8)*64
#pragma unroll
        for (int j = 0; j < 4; j++)
            g_opre[(size_t)(b * Ntok + np) * Cc + cbase + e0 + j] = acc[i][j] * scale;
    }
}

// ---------------- launch ----------------
extern "C" void kernel_launch(void* const* d_in, const int* in_sizes, int n_in,
                              void* d_out, int out_size)
{
    const float* query = (const float*)d_in[0];
    const float* Wq = (const float*)d_in[1];
    const float* bq = (const float*)d_in[2];
    const float* Wk = (const float*)d_in[3];
    const float* bk = (const float*)d_in[4];
    const float* Wv = (const float*)d_in[5];
    const float* bv = (const float*)d_in[6];
    const float* Wo = (const float*)d_in[7];
    const float* bo = (const float*)d_in[8];
    const float* temp = (const float*)d_in[9];
    float* out = (float*)d_out;

    dim3 gg(Cc / 128, (Ntok * Bb) / 128);   // (4, 256)

    sgemm_k<0><<<gg, 256>>>(query, Wq, bq, nullptr, nullptr);
    sgemm_k<1><<<gg, 256>>>(query, Wk, bk, nullptr, nullptr);
    sgemm_k<2><<<gg, 256>>>(query, Wv, bv, nullptr, nullptr);

    k_colsum<<<dim3(8, BH), 256>>>(0);
    k_red<<<(BH * Dd + 255) / 256, 256>>>(0);
    k_rownorm<<<(BH * Ntok) / 8, 256>>>();
    k_colsum<<<dim3(8, BH), 256>>>(1);
    k_red<<<(BH * Dd + 255) / 256, 256>>>(1);
    k_conserved<<<(BH * Ntok) / 8, 256>>>();
    k_softmax<<<BH, 256>>>(temp);
    k_kv<<<dim3(8, BH), 256>>>();
    k_kvred<<<(BH * Dd * Dd + 255) / 256, 256>>>();
    k_outupd<<<dim3(64, BH), 256>>>();

    sgemm_k<3><<<gg, 256>>>(nullptr, Wo, bo, query, out);
}

// round 3
// speedup vs baseline: 2.5368x; 2.5368x over previous
#include <cuda_runtime.h>
#include <cuda_bf16.h>
#include <math.h>
#include <stdint.h>

#define Ntok 4096
#define Bb   8
#define Cc   512
#define Hh   8
#define Dd   64
#define BH   64          // B*H
#define EPSf 1e-6f
#define NCHUNK 24        // 3 terms * 512 K / 64 per chunk

// ---------------- scratch (static device arrays; no allocation) ----------------
__device__ float g_q[BH * Ntok * Dd];      // (B,H,N,D) sigmoid(q proj)
__device__ float g_k[BH * Ntok * Dd];
__device__ float g_v[BH * Ntok * Dd];
__device__ float g_opre[Bb * Ntok * Cc];   // (B,N,C) pre-output
__device__ float g_ksum[BH * Dd], g_qsum[BH * Dd];
__device__ float g_kso[BH * Dd],  g_qsi[BH * Dd];
__device__ float g_si[BH * Ntok], g_so[BH * Ntok];
__device__ float g_sa[BH * Ntok], g_cs[BH * Ntok], g_comp[BH * Ntok];
__device__ float g_kpart[8 * BH * Dd], g_qpart[8 * BH * Dd];
__device__ float g_kv[BH * Dd * Dd];
__device__ float g_kvpart[8 * BH * Dd * Dd];

// bf16 split operands
__device__ __nv_bfloat16 g_Ahi[32768 * 512];
__device__ __nv_bfloat16 g_Alo[32768 * 512];
__device__ __nv_bfloat16 g_Ohi[32768 * 512];
__device__ __nv_bfloat16 g_Olo[32768 * 512];
// B operands: [proj][n (512)][k' (1536)] ; k' = [Whi(512) | Wlo(512) | Whi(512)]
__device__ __nv_bfloat16 g_B[4 * 512 * 1536];

// ---------------- PTX helpers (base-arch only: cp.async, ldmatrix, mma.sync) ----------------
__device__ __forceinline__ uint32_t smem_u32(const void* p) {
    uint32_t a;
    asm("{ .reg .u64 t; cvta.to.shared.u64 t, %1; cvt.u32.u64 %0, t; }" : "=r"(a) : "l"(p));
    return a;
}
__device__ __forceinline__ void cp16(uint32_t dst, const void* src) {
    asm volatile("cp.async.cg.shared.global [%0], [%1], 16;" :: "r"(dst), "l"(src) : "memory");
}
__device__ __forceinline__ void cp_commit() {
    asm volatile("cp.async.commit_group;" ::: "memory");
}
__device__ __forceinline__ void cp_wait2() {
    asm volatile("cp.async.wait_group 2;" ::: "memory");
}
__device__ __forceinline__ void ldm4(uint32_t* r, uint32_t addr) {
    asm volatile("ldmatrix.sync.aligned.m8n8.x4.shared.b16 {%0,%1,%2,%3}, [%4];"
                 : "=r"(r[0]), "=r"(r[1]), "=r"(r[2]), "=r"(r[3]) : "r"(addr));
}
__device__ __forceinline__ void mma16816(float* c, const uint32_t* a, const uint32_t* b) {
    asm volatile(
        "mma.sync.aligned.m16n8k16.row.col.f32.bf16.bf16.f32 "
        "{%0,%1,%2,%3}, {%4,%5,%6,%7}, {%8,%9}, {%0,%1,%2,%3};"
        : "+f"(c[0]), "+f"(c[1]), "+f"(c[2]), "+f"(c[3])
        : "r"(a[0]), "r"(a[1]), "r"(a[2]), "r"(a[3]), "r"(b[0]), "r"(b[1]));
}

// ---------------- conversion kernels ----------------
__global__ void k_split(const float* __restrict__ src,
                        __nv_bfloat16* __restrict__ hi, __nv_bfloat16* __restrict__ lo)
{
    int i = blockIdx.x * blockDim.x + threadIdx.x;
    float4 v = ((const float4*)src)[i];
    float h0 = __bfloat162float(__float2bfloat16(v.x));
    float h1 = __bfloat162float(__float2bfloat16(v.y));
    float h2 = __bfloat162float(__float2bfloat16(v.z));
    float h3 = __bfloat162float(__float2bfloat16(v.w));
    __nv_bfloat162* hp = (__nv_bfloat162*)hi;
    __nv_bfloat162* lp = (__nv_bfloat162*)lo;
    hp[2 * i]     = __nv_bfloat162(__float2bfloat16(h0), __float2bfloat16(h1));
    hp[2 * i + 1] = __nv_bfloat162(__float2bfloat16(h2), __float2bfloat16(h3));
    lp[2 * i]     = __nv_bfloat162(__float2bfloat16(v.x - h0), __float2bfloat16(v.y - h1));
    lp[2 * i + 1] = __nv_bfloat162(__float2bfloat16(v.z - h2), __float2bfloat16(v.w - h3));
}

__global__ void k_convW(const float* __restrict__ W, __nv_bfloat16* __restrict__ Bop)
{
    __shared__ float t[32][33];
    const int k0 = blockIdx.y * 32, n0 = blockIdx.x * 32;
    const int tx = threadIdx.x, ty = threadIdx.y;  // (32,8)
    for (int j = ty; j < 32; j += 8) t[j][tx] = W[(size_t)(k0 + j) * 512 + n0 + tx];
    __syncthreads();
    for (int j = ty; j < 32; j += 8) {
        float x = t[tx][j];   // W[k0+tx][n0+j]
        __nv_bfloat16 h = __float2bfloat16(x);
        __nv_bfloat16 l = __float2bfloat16(x - __bfloat162float(h));
        size_t base = (size_t)(n0 + j) * 1536 + (k0 + tx);
        Bop[base] = h; Bop[base + 512] = l; Bop[base + 1024] = h;
    }
}

// ---------------- mma.sync GEMM: D[32768,512] = A'[.,1536] @ B'^T ----------------
// MODE 0: q (sigmoid -> g_q), 1: k -> g_k, 2: v -> g_v, 3: out (+bias+resid -> d_out)
template <int MODE>
__global__ void __launch_bounds__(256) gemm_tc(
    const __nv_bfloat16* __restrict__ Ahi, const __nv_bfloat16* __restrict__ Alo,
    const __nv_bfloat16* __restrict__ Bop,
    const float* __restrict__ bias, const float* __restrict__ resid,
    float* __restrict__ out)
{
    extern __shared__ char dyn[];
    const uint32_t sbase = (smem_u32(dyn) + 1023u) & ~1023u;
    const int tid = threadIdx.x;
    const int wid = tid >> 5, lane = tid & 31;
    const int bn = blockIdx.x * 128, bm = blockIdx.y * 128;
    const int warpM = wid & 3, warpN = wid >> 2;   // 4 x 2 warps -> 32x64 warp tile

    float acc[2][8][4];
#pragma unroll
    for (int mf = 0; mf < 2; mf++)
#pragma unroll
        for (int nf = 0; nf < 8; nf++)
#pragma unroll
            for (int i = 0; i < 4; i++) acc[mf][nf][i] = 0.f;

    // ldmatrix per-lane rows (fixed across chunks)
    int aRow[2], bRow[4];
#pragma unroll
    for (int mf = 0; mf < 2; mf++)
        aRow[mf] = warpM * 32 + mf * 16 + (lane & 7) + ((lane >> 3) & 1) * 8;
    const int aHi = lane >> 4;           // cc offset for A (which k-half)
#pragma unroll
    for (int nf2 = 0; nf2 < 4; nf2++)
        bRow[nf2] = warpN * 64 + nf2 * 16 + (lane & 7) + (lane >> 4) * 8;
    const int bHi = (lane >> 3) & 1;     // cc offset for B

    auto issue = [&](int c) {
        const __nv_bfloat16* Ap = (c < 16) ? Ahi : Alo;
        const int akoff = (c & 7) << 6;
        const uint32_t buf = sbase + (uint32_t)(c % 3) * 32768u;
#pragma unroll
        for (int t = 0; t < 4; t++) {
            int s = tid + (t << 8);
            int row = s >> 3, sc = s & 7;
            uint32_t off = row * 128 + ((sc ^ (row & 7)) << 4);
            cp16(buf + off, Ap + ((size_t)(bm + row) * 512 + akoff + sc * 8));
        }
#pragma unroll
        for (int t = 0; t < 4; t++) {
            int s = tid + (t << 8);
            int row = s >> 3, sc = s & 7;
            uint32_t off = row * 128 + ((sc ^ (row & 7)) << 4);
            cp16(buf + 16384u + off, Bop + ((size_t)(bn + row) * 1536 + (c << 6) + sc * 8));
        }
    };

    issue(0); cp_commit();
    issue(1); cp_commit();

    for (int c = 0; c < NCHUNK; c++) {
        if (c + 2 < NCHUNK) issue(c + 2);
        cp_commit();
        cp_wait2();
        __syncthreads();

        const uint32_t abuf = sbase + (uint32_t)(c % 3) * 32768u;
        const uint32_t bbuf = abuf + 16384u;
#pragma unroll
        for (int ks = 0; ks < 4; ks++) {
            uint32_t a[2][4], b[4][4];
#pragma unroll
            for (int mf = 0; mf < 2; mf++) {
                const int row = aRow[mf];
                const int cc = 2 * ks + aHi;
                ldm4(a[mf], abuf + row * 128 + ((cc ^ (row & 7)) << 4));
            }
#pragma unroll
            for (int nf2 = 0; nf2 < 4; nf2++) {
                const int row = bRow[nf2];
                const int cc = 2 * ks + bHi;
                ldm4(b[nf2], bbuf + row * 128 + ((cc ^ (row & 7)) << 4));
            }
#pragma unroll
            for (int mf = 0; mf < 2; mf++)
#pragma unroll
                for (int nf = 0; nf < 8; nf++)
                    mma16816(acc[mf][nf], a[mf], &b[nf >> 1][(nf & 1) * 2]);
        }
        __syncthreads();
    }

    // ---------------- epilogue ----------------
    const int r0base = bm + warpM * 32 + (lane >> 2);
    const int cb = bn + warpN * 64 + ((lane & 3) << 1);
#pragma unroll
    for (int mf = 0; mf < 2; mf++)
#pragma unroll
        for (int half = 0; half < 2; half++) {
            const int r = r0base + mf * 16 + half * 8;
#pragma unroll
            for (int nf = 0; nf < 8; nf++) {
                const int c0 = cb + nf * 8;
                float2 v;
                v.x = acc[mf][nf][half * 2 + 0] + bias[c0];
                v.y = acc[mf][nf][half * 2 + 1] + bias[c0 + 1];
                if (MODE <= 2) {
                    if (MODE == 0 || MODE == 1) {
                        v.x = 1.f / (1.f + expf(-v.x));
                        v.y = 1.f / (1.f + expf(-v.y));
                    }
                    float* dstg = (MODE == 0) ? g_q : (MODE == 1) ? g_k : g_v;
                    const int n = r >> 3, bb = r & 7;
                    const int h = c0 >> 6, d = c0 & 63;
                    const size_t o = ((size_t)((bb << 3) | h) * Ntok + n) * Dd + d;
                    *(float2*)(dstg + o) = v;
                } else {
                    const int bb = r >> 12, n = r & 4095;
                    const size_t o = (size_t)((n << 3) | bb) * Cc + c0;
                    float2 rs = *(const float2*)(resid + o);
                    v.x += rs.x; v.y += rs.y;
                    *(float2*)(out + o) = v;
                }
            }
        }
}

// ---------------- mid-section kernels (unchanged from round 1) ----------------
__global__ void k_colsum(int weighted)
{
    const int bh = blockIdx.y, chunk = blockIdx.x;
    const int d = threadIdx.x & 63, p = threadIdx.x >> 6;
    const float* kb = g_k + (size_t)bh * Ntok * Dd;
    const float* qb = g_q + (size_t)bh * Ntok * Dd;
    float ak = 0.f, aq = 0.f;
    const int s0 = chunk * 512;
    for (int s = s0 + p; s < s0 + 512; s += 4) {
        float wk = 1.f, wq = 1.f;
        if (weighted) { wk = g_so[bh * Ntok + s]; wq = g_si[bh * Ntok + s]; }
        ak += kb[(size_t)s * Dd + d] * wk;
        aq += qb[(size_t)s * Dd + d] * wq;
    }
    __shared__ float sk[4][64], sq[4][64];
    sk[p][d] = ak; sq[p][d] = aq;
    __syncthreads();
    if (p == 0) {
        g_kpart[(chunk * BH + bh) * Dd + d] = sk[0][d] + sk[1][d] + sk[2][d] + sk[3][d];
        g_qpart[(chunk * BH + bh) * Dd + d] = sq[0][d] + sq[1][d] + sq[2][d] + sq[3][d];
    }
}

__global__ void k_red(int mode)
{
    const int i = blockIdx.x * blockDim.x + threadIdx.x;
    if (i >= BH * Dd) return;
    float sk = 0.f, sq = 0.f;
#pragma unroll
    for (int c = 0; c < 8; c++) {
        sk += g_kpart[c * BH * Dd + i];
        sq += g_qpart[c * BH * Dd + i];
    }
    if (mode == 0) { g_ksum[i] = sk; g_qsum[i] = sq; }
    else           { g_kso[i]  = sk; g_qsi[i]  = sq; }
}

__global__ void k_rownorm()
{
    const int w = (blockIdx.x * blockDim.x + threadIdx.x) >> 5;
    const int lane = threadIdx.x & 31;
    const int bh = w >> 12;
    const float* qr  = g_q + (size_t)w * Dd;
    const float* kr  = g_k + (size_t)w * Dd;
    const float* ksv = g_ksum + bh * Dd;
    const float* qsv = g_qsum + bh * Dd;
    float s1 = (qr[lane] + EPSf) * (ksv[lane] + EPSf)
             + (qr[lane + 32] + EPSf) * (ksv[lane + 32] + EPSf);
    float s2 = (kr[lane] + EPSf) * (qsv[lane] + EPSf)
             + (kr[lane + 32] + EPSf) * (qsv[lane + 32] + EPSf);
#pragma unroll
    for (int o = 16; o > 0; o >>= 1) {
        s1 += __shfl_xor_sync(0xffffffffu, s1, o);
        s2 += __shfl_xor_sync(0xffffffffu, s2, o);
    }
    if (lane == 0) {
        g_si[w] = 1.f / (s1 + EPSf);
        g_so[w] = 1.f / (s2 + EPSf);
    }
}

__global__ void k_conserved()
{
    const int w = (blockIdx.x * blockDim.x + threadIdx.x) >> 5;
    const int lane = threadIdx.x & 31;
    const int bh = w >> 12;
    const float* qr  = g_q + (size_t)w * Dd;
    const float* kr  = g_k + (size_t)w * Dd;
    const float* kso = g_kso + bh * Dd;
    const float* qsi = g_qsi + bh * Dd;
    float s1 = (qr[lane] + EPSf) * (kso[lane] + EPSf)
             + (qr[lane + 32] + EPSf) * (kso[lane + 32] + EPSf);
    float s2 = (kr[lane] + EPSf) * (qsi[lane] + EPSf)
             + (kr[lane + 32] + EPSf) * (qsi[lane + 32] + EPSf);
#pragma unroll
    for (int o = 16; o > 0; o >>= 1) {
        s1 += __shfl_xor_sync(0xffffffffu, s1, o);
        s2 += __shfl_xor_sync(0xffffffffu, s2, o);
    }
    if (lane == 0) {
        float cs_sink = s1 + EPSf;
        g_sa[w] = 1.f / (1.f + expf(-cs_sink));
        float cs_src = s2 + EPSf;
        g_cs[w] = fminf(1.f, fmaxf(-1.f, cs_src));
    }
}

__global__ void k_softmax(const float* __restrict__ tptr)
{
    const int bh = blockIdx.x, t = threadIdx.x;
    const float* cs = g_cs + bh * Ntok;
    const float invT = 1.f / tptr[0];
    float v[16];
    float lmax = -3.4e38f;
#pragma unroll
    for (int i = 0; i < 16; i++) {
        v[i] = cs[t + (i << 8)];
        lmax = fmaxf(lmax, v[i]);
    }
    __shared__ float red[256];
    red[t] = lmax; __syncthreads();
    for (int o = 128; o > 0; o >>= 1) { if (t < o) red[t] = fmaxf(red[t], red[t + o]); __syncthreads(); }
    const float mx = red[0];
    __syncthreads();
    float lsum = 0.f;
#pragma unroll
    for (int i = 0; i < 16; i++) { v[i] = expf((v[i] - mx) * invT); lsum += v[i]; }
    red[t] = lsum; __syncthreads();
    for (int o = 128; o > 0; o >>= 1) { if (t < o) red[t] += red[t + o]; __syncthreads(); }
    const float scale = (float)Cc / red[0];
#pragma unroll
    for (int i = 0; i < 16; i++) g_comp[bh * Ntok + t + (i << 8)] = v[i] * scale;
}

__global__ void __launch_bounds__(256) k_kv()
{
    const int bh = blockIdx.y, chunk = blockIdx.x;
    __shared__ float ks[32][64];
    __shared__ float ws[32][64];
    const int tid = threadIdx.x;
    const int lr = tid >> 3;
    const int lc = (tid & 7) << 3;
    const size_t base = (size_t)bh * Ntok * Dd;
    const int d0 = (tid & 15) << 2, e0 = (tid >> 4) << 2;
    float acc[4][4] = {};
    for (int s0 = chunk * 512; s0 < chunk * 512 + 512; s0 += 32) {
        const int s = s0 + lr;
        const float cmp = g_comp[bh * Ntok + s];
        float4 ka = *(const float4*)(g_k + base + (size_t)s * Dd + lc);
        float4 kb = *(const float4*)(g_k + base + (size_t)s * Dd + lc + 4);
        float4 va = *(const float4*)(g_v + base + (size_t)s * Dd + lc);
        float4 vb = *(const float4*)(g_v + base + (size_t)s * Dd + lc + 4);
        *(float4*)&ks[lr][lc]     = ka;
        *(float4*)&ks[lr][lc + 4] = kb;
        va.x *= cmp; va.y *= cmp; va.z *= cmp; va.w *= cmp;
        vb.x *= cmp; vb.y *= cmp; vb.z *= cmp; vb.w *= cmp;
        *(float4*)&ws[lr][lc]     = va;
        *(float4*)&ws[lr][lc + 4] = vb;
        __syncthreads();
#pragma unroll
        for (int ss = 0; ss < 32; ss++) {
            float4 kf = *(const float4*)&ks[ss][d0];
            float4 wf = *(const float4*)&ws[ss][e0];
            float krr[4] = {kf.x, kf.y, kf.z, kf.w};
            float wr[4] = {wf.x, wf.y, wf.z, wf.w};
#pragma unroll
            for (int i = 0; i < 4; i++)
#pragma unroll
                for (int j = 0; j < 4; j++)
                    acc[i][j] = fmaf(krr[i], wr[j], acc[i][j]);
        }
        __syncthreads();
    }
    float* dst = g_kvpart + ((size_t)chunk * BH + bh) * Dd * Dd;
#pragma unroll
    for (int i = 0; i < 4; i++)
#pragma unroll
        for (int j = 0; j < 4; j++)
            dst[(d0 + i) * Dd + e0 + j] = acc[i][j];
}

__global__ void k_kvred()
{
    const int i = blockIdx.x * blockDim.x + threadIdx.x;
    if (i >= BH * Dd * Dd) return;
    float s = 0.f;
#pragma unroll
    for (int c = 0; c < 8; c++) s += g_kvpart[(size_t)c * BH * Dd * Dd + i];
    g_kv[i] = s;
}

__global__ void __launch_bounds__(256) k_outupd()
{
    const int bh = blockIdx.y, nt = blockIdx.x;
    const int b = bh >> 3, h = bh & 7;
    __shared__ float kvs[64][64];
    __shared__ float qsT[64][68];
    const int tid = threadIdx.x;

    const float4* kvsrc = (const float4*)(g_kv + (size_t)bh * (Dd * Dd));
    for (int i = tid; i < 1024; i += 256) ((float4*)kvs)[i] = kvsrc[i];

    const int lr = tid >> 3;
    const int lc = (tid & 7) << 3;
    const float* qb = g_q + (size_t)bh * Ntok * Dd + (size_t)(nt * 64) * Dd;
#pragma unroll
    for (int rr = lr; rr < 64; rr += 32) {
        float4 q0 = *(const float4*)(qb + rr * Dd + lc);
        float4 q1 = *(const float4*)(qb + rr * Dd + lc + 4);
        qsT[lc + 0][rr] = q0.x; qsT[lc + 1][rr] = q0.y;
        qsT[lc + 2][rr] = q0.z; qsT[lc + 3][rr] = q0.w;
        qsT[lc + 4][rr] = q1.x; qsT[lc + 5][rr] = q1.y;
        qsT[lc + 6][rr] = q1.z; qsT[lc + 7][rr] = q1.w;
    }
    __syncthreads();

    const int n0 = (tid & 15) << 2, e0 = (tid >> 4) << 2;
    float acc[4][4] = {};
#pragma unroll
    for (int d = 0; d < 64; d++) {
        float4 qa = *(const float4*)&qsT[d][n0];
        float4 kf = *(const float4*)&kvs[d][e0];
        float qr[4] = {qa.x, qa.y, qa.z, qa.w};
        float krr[4] = {kf.x, kf.y, kf.z, kf.w};
#pragma unroll
        for (int i = 0; i < 4; i++)
#pragma unroll
            for (int j = 0; j < 4; j++)
                acc[i][j] = fmaf(qr[i], krr[j], acc[i][j]);
    }

#pragma unroll
    for (int i = 0; i < 4; i++) {
        const int n = nt * 64 + n0 + i;
        const float scale = g_si[bh * Ntok + n] * g_sa[bh * Ntok + n];
        const int np = (h << 9) | (n >> 3);
        const int cbase = (n & 7) << 6;
#pragma unroll
        for (int j = 0; j < 4; j++)
            g_opre[(size_t)(b * Ntok + np) * Cc + cbase + e0 + j] = acc[i][j] * scale;
    }
}

// ---------------- launch ----------------
extern "C" void kernel_launch(void* const* d_in, const int* in_sizes, int n_in,
                              void* d_out, int out_size)
{
    const float* query = (const float*)d_in[0];
    const float* Wq = (const float*)d_in[1];
    const float* bq = (const float*)d_in[2];
    const float* Wk = (const float*)d_in[3];
    const float* bk = (const float*)d_in[4];
    const float* Wv = (const float*)d_in[5];
    const float* bv = (const float*)d_in[6];
    const float* Wo = (const float*)d_in[7];
    const float* bo = (const float*)d_in[8];
    const float* temp = (const float*)d_in[9];
    float* out = (float*)d_out;

    const int DSMEM = 3 * 32768 + 1024;
    cudaFuncSetAttribute(gemm_tc<0>, cudaFuncAttributeMaxDynamicSharedMemorySize, DSMEM);
    cudaFuncSetAttribute(gemm_tc<1>, cudaFuncAttributeMaxDynamicSharedMemorySize, DSMEM);
    cudaFuncSetAttribute(gemm_tc<2>, cudaFuncAttributeMaxDynamicSharedMemorySize, DSMEM);
    cudaFuncSetAttribute(gemm_tc<3>, cudaFuncAttributeMaxDynamicSharedMemorySize, DSMEM);

    __nv_bfloat16 *pAhi, *pAlo, *pOhi, *pOlo, *pB;
    cudaGetSymbolAddress((void**)&pAhi, g_Ahi);
    cudaGetSymbolAddress((void**)&pAlo, g_Alo);
    cudaGetSymbolAddress((void**)&pOhi, g_Ohi);
    cudaGetSymbolAddress((void**)&pOlo, g_Olo);
    cudaGetSymbolAddress((void**)&pB,  g_B);
    float* popre;
    cudaGetSymbolAddress((void**)&popre, g_opre);

    dim3 gg(4, 256);            // N-tiles x M-tiles
    dim3 wblk(32, 8), wgrd(16, 16);

    // operand conversion
    k_split<<<16384, 256>>>(query, pAhi, pAlo);
    k_convW<<<wgrd, wblk>>>(Wq, pB + 0 * 512 * 1536);
    k_convW<<<wgrd, wblk>>>(Wk, pB + 1 * 512 * 1536);
    k_convW<<<wgrd, wblk>>>(Wv, pB + 2 * 512 * 1536);
    k_convW<<<wgrd, wblk>>>(Wo, pB + 3 * 512 * 1536);

    gemm_tc<0><<<gg, 256, DSMEM>>>(pAhi, pAlo, pB + 0 * 512 * 1536, bq, nullptr, nullptr);
    gemm_tc<1><<<gg, 256, DSMEM>>>(pAhi, pAlo, pB + 1 * 512 * 1536, bk, nullptr, nullptr);
    gemm_tc<2><<<gg, 256, DSMEM>>>(pAhi, pAlo, pB + 2 * 512 * 1536, bv, nullptr, nullptr);

    k_colsum<<<dim3(8, BH), 256>>>(0);
    k_red<<<(BH * Dd + 255) / 256, 256>>>(0);
    k_rownorm<<<(BH * Ntok) / 8, 256>>>();
    k_colsum<<<dim3(8, BH), 256>>>(1);
    k_red<<<(BH * Dd + 255) / 256, 256>>>(1);
    k_conserved<<<(BH * Ntok) / 8, 256>>>();
    k_softmax<<<BH, 256>>>(temp);
    k_kv<<<dim3(8, BH), 256>>>();
    k_kvred<<<(BH * Dd * Dd + 255) / 256, 256>>>();
    k_outupd<<<dim3(64, BH), 256>>>();

    k_split<<<16384, 256>>>(popre, pOhi, pOlo);
    gemm_tc<3><<<gg, 256, DSMEM>>>(pOhi, pOlo, pB + 3 * 512 * 1536, bo, query, out);
}

// round 4
// speedup vs baseline: 2.9213x; 1.1516x over previous
#include <cuda_runtime.h>
#include <cuda_fp16.h>
#include <math.h>
#include <stdint.h>

#define Ntok 4096
#define Bb   8
#define Cc   512
#define Hh   8
#define Dd   64
#define BH   64          // B*H
#define EPSf 1e-6f
#define NCHUNK 16        // 2 terms * 512 K / 64 per chunk

// ---------------- scratch (static device arrays; no allocation) ----------------
__device__ float g_q[BH * Ntok * Dd];      // (B,H,N,D) sigmoid(q proj)
__device__ float g_k[BH * Ntok * Dd];
__device__ float g_v[BH * Ntok * Dd];
__device__ float g_ksum[BH * Dd], g_qsum[BH * Dd];
__device__ float g_kso[BH * Dd],  g_qsi[BH * Dd];
__device__ float g_si[BH * Ntok], g_so[BH * Ntok];
__device__ float g_sa[BH * Ntok], g_cs[BH * Ntok], g_comp[BH * Ntok];
__device__ float g_kpart[8 * BH * Dd], g_qpart[8 * BH * Dd];
__device__ float g_kv[BH * Dd * Dd];
__device__ float g_kvpart[8 * BH * Dd * Dd];

// fp16 split operands
__device__ __half g_Ahi[32768 * 512];
__device__ __half g_Alo[32768 * 512];
__device__ __half g_Ohi[32768 * 512];
__device__ __half g_Olo[32768 * 512];
// B operands: [proj][n (512)][k' (1024)] ; k' = [Wh(512) | Wh(512)]
__device__ __half g_B[4 * 512 * 1024];

// ---------------- PTX helpers (base-arch only) ----------------
__device__ __forceinline__ uint32_t smem_u32(const void* p) {
    uint32_t a;
    asm("{ .reg .u64 t; cvta.to.shared.u64 t, %1; cvt.u32.u64 %0, t; }" : "=r"(a) : "l"(p));
    return a;
}
__device__ __forceinline__ void cp16(uint32_t dst, const void* src) {
    asm volatile("cp.async.cg.shared.global [%0], [%1], 16;" :: "r"(dst), "l"(src) : "memory");
}
__device__ __forceinline__ void cp_commit() {
    asm volatile("cp.async.commit_group;" ::: "memory");
}
__device__ __forceinline__ void cp_wait2() {
    asm volatile("cp.async.wait_group 2;" ::: "memory");
}
__device__ __forceinline__ void ldm4(uint32_t* r, uint32_t addr) {
    asm volatile("ldmatrix.sync.aligned.m8n8.x4.shared.b16 {%0,%1,%2,%3}, [%4];"
                 : "=r"(r[0]), "=r"(r[1]), "=r"(r[2]), "=r"(r[3]) : "r"(addr));
}
__device__ __forceinline__ void mma16816(float* c, const uint32_t* a, const uint32_t* b) {
    asm volatile(
        "mma.sync.aligned.m16n8k16.row.col.f32.f16.f16.f32 "
        "{%0,%1,%2,%3}, {%4,%5,%6,%7}, {%8,%9}, {%0,%1,%2,%3};"
        : "+f"(c[0]), "+f"(c[1]), "+f"(c[2]), "+f"(c[3])
        : "r"(a[0]), "r"(a[1]), "r"(a[2]), "r"(a[3]), "r"(b[0]), "r"(b[1]));
}

// ---------------- conversion kernels ----------------
__global__ void k_split(const float* __restrict__ src,
                        __half* __restrict__ hi, __half* __restrict__ lo)
{
    int i = blockIdx.x * blockDim.x + threadIdx.x;
    float4 v = ((const float4*)src)[i];
    __half h0 = __float2half_rn(v.x), h1 = __float2half_rn(v.y);
    __half h2 = __float2half_rn(v.z), h3 = __float2half_rn(v.w);
    __half2* hp = (__half2*)hi;
    __half2* lp = (__half2*)lo;
    hp[2 * i]     = __halves2half2(h0, h1);
    hp[2 * i + 1] = __halves2half2(h2, h3);
    lp[2 * i]     = __halves2half2(__float2half_rn(v.x - __half2float(h0)),
                                   __float2half_rn(v.y - __half2float(h1)));
    lp[2 * i + 1] = __halves2half2(__float2half_rn(v.z - __half2float(h2)),
                                   __float2half_rn(v.w - __half2float(h3)));
}

__global__ void k_convW(const float* __restrict__ Wq, const float* __restrict__ Wk,
                        const float* __restrict__ Wv, const float* __restrict__ Wo,
                        __half* __restrict__ Bop)
{
    const float* W = (blockIdx.z == 0) ? Wq : (blockIdx.z == 1) ? Wk
                   : (blockIdx.z == 2) ? Wv : Wo;
    __half* Bp = Bop + (size_t)blockIdx.z * (512 * 1024);
    __shared__ float t[32][33];
    const int k0 = blockIdx.y * 32, n0 = blockIdx.x * 32;
    const int tx = threadIdx.x, ty = threadIdx.y;  // (32,8)
    for (int j = ty; j < 32; j += 8) t[j][tx] = W[(size_t)(k0 + j) * 512 + n0 + tx];
    __syncthreads();
    for (int j = ty; j < 32; j += 8) {
        __half h = __float2half_rn(t[tx][j]);   // W[k0+tx][n0+j]
        size_t base = (size_t)(n0 + j) * 1024 + (k0 + tx);
        Bp[base] = h; Bp[base + 512] = h;
    }
}

// ---------------- mma.sync GEMM: D[32768,512] = A'[.,1024] @ B'^T ----------------
// mode 0: q (sigmoid -> g_q), 1: k -> g_k, 2: v -> g_v, 3: out (+bias+resid -> d_out)
__global__ void __launch_bounds__(256) gemm_tc(
    const __half* __restrict__ Ahi, const __half* __restrict__ Alo,
    const __half* __restrict__ Bbase,
    const float* __restrict__ b0, const float* __restrict__ b1, const float* __restrict__ b2,
    const float* __restrict__ resid, float* __restrict__ out, int modeBase)
{
    extern __shared__ char dyn[];
    const uint32_t sbase = (smem_u32(dyn) + 1023u) & ~1023u;
    const int tid = threadIdx.x;
    const int wid = tid >> 5, lane = tid & 31;
    const int bn = blockIdx.x * 128, bm = blockIdx.y * 128;
    const int mode = modeBase + blockIdx.z;
    const __half* Bop = Bbase + (size_t)blockIdx.z * (512 * 1024);
    const float* bias = (mode == 1) ? b1 : (mode == 2) ? b2 : b0;
    const int warpM = wid & 3, warpN = wid >> 2;   // 4 x 2 warps -> 32x64 warp tile

    float acc[2][8][4];
#pragma unroll
    for (int mf = 0; mf < 2; mf++)
#pragma unroll
        for (int nf = 0; nf < 8; nf++)
#pragma unroll
            for (int i = 0; i < 4; i++) acc[mf][nf][i] = 0.f;

    int aRow[2], bRow[4];
#pragma unroll
    for (int mf = 0; mf < 2; mf++)
        aRow[mf] = warpM * 32 + mf * 16 + (lane & 7) + ((lane >> 3) & 1) * 8;
    const int aHi = lane >> 4;
#pragma unroll
    for (int nf2 = 0; nf2 < 4; nf2++)
        bRow[nf2] = warpN * 64 + nf2 * 16 + (lane & 7) + (lane >> 4) * 8;
    const int bHi = (lane >> 3) & 1;

    auto issue = [&](int c) {
        const __half* Ap = (c < 8) ? Ahi : Alo;
        const int akoff = (c & 7) << 6;
        const uint32_t buf = sbase + (uint32_t)(c % 3) * 32768u;
#pragma unroll
        for (int t = 0; t < 4; t++) {
            int s = tid + (t << 8);
            int row = s >> 3, sc = s & 7;
            uint32_t off = row * 128 + ((sc ^ (row & 7)) << 4);
            cp16(buf + off, Ap + ((size_t)(bm + row) * 512 + akoff + sc * 8));
        }
#pragma unroll
        for (int t = 0; t < 4; t++) {
            int s = tid + (t << 8);
            int row = s >> 3, sc = s & 7;
            uint32_t off = row * 128 + ((sc ^ (row & 7)) << 4);
            cp16(buf + 16384u + off, Bop + ((size_t)(bn + row) * 1024 + (c << 6) + sc * 8));
        }
    };

    issue(0); cp_commit();
    issue(1); cp_commit();

    for (int c = 0; c < NCHUNK; c++) {
        if (c + 2 < NCHUNK) issue(c + 2);
        cp_commit();
        cp_wait2();
        __syncthreads();

        const uint32_t abuf = sbase + (uint32_t)(c % 3) * 32768u;
        const uint32_t bbuf = abuf + 16384u;
#pragma unroll
        for (int ks = 0; ks < 4; ks++) {
            uint32_t a[2][4], b[4][4];
#pragma unroll
            for (int mf = 0; mf < 2; mf++) {
                const int row = aRow[mf];
                const int cc = 2 * ks + aHi;
                ldm4(a[mf], abuf + row * 128 + ((cc ^ (row & 7)) << 4));
            }
#pragma unroll
            for (int nf2 = 0; nf2 < 4; nf2++) {
                const int row = bRow[nf2];
                const int cc = 2 * ks + bHi;
                ldm4(b[nf2], bbuf + row * 128 + ((cc ^ (row & 7)) << 4));
            }
#pragma unroll
            for (int mf = 0; mf < 2; mf++)
#pragma unroll
                for (int nf = 0; nf < 8; nf++)
                    mma16816(acc[mf][nf], a[mf], &b[nf >> 1][(nf & 1) * 2]);
        }
        __syncthreads();
    }

    // ---------------- epilogue ----------------
    float* dstg = (mode == 0) ? g_q : (mode == 1) ? g_k : g_v;
    const int r0base = bm + warpM * 32 + (lane >> 2);
    const int cb = bn + warpN * 64 + ((lane & 3) << 1);
#pragma unroll
    for (int mf = 0; mf < 2; mf++)
#pragma unroll
        for (int half = 0; half < 2; half++) {
            const int r = r0base + mf * 16 + half * 8;
#pragma unroll
            for (int nf = 0; nf < 8; nf++) {
                const int c0 = cb + nf * 8;
                float2 v;
                v.x = acc[mf][nf][half * 2 + 0] + bias[c0];
                v.y = acc[mf][nf][half * 2 + 1] + bias[c0 + 1];
                if (mode <= 2) {
                    if (mode <= 1) {
                        v.x = 1.f / (1.f + expf(-v.x));
                        v.y = 1.f / (1.f + expf(-v.y));
                    }
                    const int n = r >> 3, bb = r & 7;
                    const int h = c0 >> 6, d = c0 & 63;
                    const size_t o = ((size_t)((bb << 3) | h) * Ntok + n) * Dd + d;
                    *(float2*)(dstg + o) = v;
                } else {
                    const int bb = r >> 12, n = r & 4095;
                    const size_t o = (size_t)((n << 3) | bb) * Cc + c0;
                    float2 rs = *(const float2*)(resid + o);
                    v.x += rs.x; v.y += rs.y;
                    *(float2*)(out + o) = v;
                }
            }
        }
}

// ---------------- plain column sums over s ----------------
__global__ void k_colsum()
{
    const int bh = blockIdx.y, chunk = blockIdx.x;
    const int d = threadIdx.x & 63, p = threadIdx.x >> 6;
    const float* kb = g_k + (size_t)bh * Ntok * Dd;
    const float* qb = g_q + (size_t)bh * Ntok * Dd;
    float ak = 0.f, aq = 0.f;
    const int s0 = chunk * 512;
    for (int s = s0 + p; s < s0 + 512; s += 4) {
        ak += kb[(size_t)s * Dd + d];
        aq += qb[(size_t)s * Dd + d];
    }
    __shared__ float sk[4][64], sq[4][64];
    sk[p][d] = ak; sq[p][d] = aq;
    __syncthreads();
    if (p == 0) {
        g_kpart[(chunk * BH + bh) * Dd + d] = sk[0][d] + sk[1][d] + sk[2][d] + sk[3][d];
        g_qpart[(chunk * BH + bh) * Dd + d] = sq[0][d] + sq[1][d] + sq[2][d] + sq[3][d];
    }
}

__global__ void k_red(int mode)
{
    const int i = blockIdx.x * blockDim.x + threadIdx.x;
    if (i >= BH * Dd) return;
    float sk = 0.f, sq = 0.f;
#pragma unroll
    for (int c = 0; c < 8; c++) {
        sk += g_kpart[c * BH * Dd + i];
        sq += g_qpart[c * BH * Dd + i];
    }
    if (mode == 0) { g_ksum[i] = sk; g_qsum[i] = sq; }
    else           { g_kso[i]  = sk; g_qsi[i]  = sq; }
}

// ---------------- fused rownorm (si/so) + weighted colsum partials ----------------
__global__ void __launch_bounds__(256) k_fuse1()
{
    const int bh = blockIdx.y, chunk = blockIdx.x;
    const int w = threadIdx.x >> 5, lane = threadIdx.x & 31;
    const float* qb = g_q + (size_t)bh * Ntok * Dd;
    const float* kb = g_k + (size_t)bh * Ntok * Dd;
    const float ks0 = g_ksum[bh * Dd + lane] + EPSf;
    const float ks1 = g_ksum[bh * Dd + lane + 32] + EPSf;
    const float qs0 = g_qsum[bh * Dd + lane] + EPSf;
    const float qs1 = g_qsum[bh * Dd + lane + 32] + EPSf;
    float aq0 = 0.f, aq1 = 0.f, ak0 = 0.f, ak1 = 0.f;
    const int s0 = chunk * 512 + w * 64;
    for (int i = 0; i < 64; i++) {
        const int s = s0 + i;
        const float qa = qb[(size_t)s * Dd + lane],  qb2 = qb[(size_t)s * Dd + lane + 32];
        const float ka = kb[(size_t)s * Dd + lane],  kb2 = kb[(size_t)s * Dd + lane + 32];
        float s1 = (qa + EPSf) * ks0 + (qb2 + EPSf) * ks1;
        float s2 = (ka + EPSf) * qs0 + (kb2 + EPSf) * qs1;
#pragma unroll
        for (int o = 16; o > 0; o >>= 1) {
            s1 += __shfl_xor_sync(0xffffffffu, s1, o);
            s2 += __shfl_xor_sync(0xffffffffu, s2, o);
        }
        const float si = 1.f / (s1 + EPSf);
        const float so = 1.f / (s2 + EPSf);
        if (lane == 0) { g_si[bh * Ntok + s] = si; g_so[bh * Ntok + s] = so; }
        aq0 += si * qa; aq1 += si * qb2;
        ak0 += so * ka; ak1 += so * kb2;
    }
    __shared__ float sQ[8][64], sK[8][64];
    sQ[w][lane] = aq0; sQ[w][lane + 32] = aq1;
    sK[w][lane] = ak0; sK[w][lane + 32] = ak1;
    __syncthreads();
    if (threadIdx.x < 64) {
        const int d = threadIdx.x;
        float sq = 0.f, sk = 0.f;
#pragma unroll
        for (int w2 = 0; w2 < 8; w2++) { sq += sQ[w2][d]; sk += sK[w2][d]; }
        g_qpart[(chunk * BH + bh) * Dd + d] = sq;   // si-weighted q sums
        g_kpart[(chunk * BH + bh) * Dd + d] = sk;   // so-weighted k sums
    }
}

__global__ void k_conserved()
{
    const int w = (blockIdx.x * blockDim.x + threadIdx.x) >> 5;
    const int lane = threadIdx.x & 31;
    const int bh = w >> 12;
    const float* qr  = g_q + (size_t)w * Dd;
    const float* kr  = g_k + (size_t)w * Dd;
    const float* kso = g_kso + bh * Dd;
    const float* qsi = g_qsi + bh * Dd;
    float s1 = (qr[lane] + EPSf) * (kso[lane] + EPSf)
             + (qr[lane + 32] + EPSf) * (kso[lane + 32] + EPSf);
    float s2 = (kr[lane] + EPSf) * (qsi[lane] + EPSf)
             + (kr[lane + 32] + EPSf) * (qsi[lane + 32] + EPSf);
#pragma unroll
    for (int o = 16; o > 0; o >>= 1) {
        s1 += __shfl_xor_sync(0xffffffffu, s1, o);
        s2 += __shfl_xor_sync(0xffffffffu, s2, o);
    }
    if (lane == 0) {
        float cs_sink = s1 + EPSf;
        g_sa[w] = 1.f / (1.f + expf(-cs_sink));
        float cs_src = s2 + EPSf;
        g_cs[w] = fminf(1.f, fmaxf(-1.f, cs_src));
    }
}

__global__ void k_softmax(const float* __restrict__ tptr)
{
    const int bh = blockIdx.x, t = threadIdx.x;
    const float* cs = g_cs + bh * Ntok;
    const float invT = 1.f / tptr[0];
    float v[16];
    float lmax = -3.4e38f;
#pragma unroll
    for (int i = 0; i < 16; i++) {
        v[i] = cs[t + (i << 8)];
        lmax = fmaxf(lmax, v[i]);
    }
    __shared__ float red[256];
    red[t] = lmax; __syncthreads();
    for (int o = 128; o > 0; o >>= 1) { if (t < o) red[t] = fmaxf(red[t], red[t + o]); __syncthreads(); }
    const float mx = red[0];
    __syncthreads();
    float lsum = 0.f;
#pragma unroll
    for (int i = 0; i < 16; i++) { v[i] = expf((v[i] - mx) * invT); lsum += v[i]; }
    red[t] = lsum; __syncthreads();
    for (int o = 128; o > 0; o >>= 1) { if (t < o) red[t] += red[t + o]; __syncthreads(); }
    const float scale = (float)Cc / red[0];
#pragma unroll
    for (int i = 0; i < 16; i++) g_comp[bh * Ntok + t + (i << 8)] = v[i] * scale;
}

__global__ void __launch_bounds__(256) k_kv()
{
    const int bh = blockIdx.y, chunk = blockIdx.x;
    __shared__ float ks[32][64];
    __shared__ float ws[32][64];
    const int tid = threadIdx.x;
    const int lr = tid >> 3;
    const int lc = (tid & 7) << 3;
    const size_t base = (size_t)bh * Ntok * Dd;
    const int d0 = (tid & 15) << 2, e0 = (tid >> 4) << 2;
    float acc[4][4] = {};
    for (int s0 = chunk * 512; s0 < chunk * 512 + 512; s0 += 32) {
        const int s = s0 + lr;
        const float cmp = g_comp[bh * Ntok + s];
        float4 ka = *(const float4*)(g_k + base + (size_t)s * Dd + lc);
        float4 kb = *(const float4*)(g_k + base + (size_t)s * Dd + lc + 4);
        float4 va = *(const float4*)(g_v + base + (size_t)s * Dd + lc);
        float4 vb = *(const float4*)(g_v + base + (size_t)s * Dd + lc + 4);
        *(float4*)&ks[lr][lc]     = ka;
        *(float4*)&ks[lr][lc + 4] = kb;
        va.x *= cmp; va.y *= cmp; va.z *= cmp; va.w *= cmp;
        vb.x *= cmp; vb.y *= cmp; vb.z *= cmp; vb.w *= cmp;
        *(float4*)&ws[lr][lc]     = va;
        *(float4*)&ws[lr][lc + 4] = vb;
        __syncthreads();
#pragma unroll
        for (int ss = 0; ss < 32; ss++) {
            float4 kf = *(const float4*)&ks[ss][d0];
            float4 wf = *(const float4*)&ws[ss][e0];
            float krr[4] = {kf.x, kf.y, kf.z, kf.w};
            float wr[4] = {wf.x, wf.y, wf.z, wf.w};
#pragma unroll
            for (int i = 0; i < 4; i++)
#pragma unroll
                for (int j = 0; j < 4; j++)
                    acc[i][j] = fmaf(krr[i], wr[j], acc[i][j]);
        }
        __syncthreads();
    }
    float* dst = g_kvpart + ((size_t)chunk * BH + bh) * Dd * Dd;
#pragma unroll
    for (int i = 0; i < 4; i++)
#pragma unroll
        for (int j = 0; j < 4; j++)
            dst[(d0 + i) * Dd + e0 + j] = acc[i][j];
}

__global__ void k_kvred()
{
    const int i = blockIdx.x * blockDim.x + threadIdx.x;
    if (i >= BH * Dd * Dd) return;
    float s = 0.f;
#pragma unroll
    for (int c = 0; c < 8; c++) s += g_kvpart[(size_t)c * BH * Dd * Dd + i];
    g_kv[i] = s;
}

// ---------------- out_update = (q @ kv) * si * sa -> fp16 hi/lo split directly ----------------
__global__ void __launch_bounds__(256) k_outupd()
{
    const int bh = blockIdx.y, nt = blockIdx.x;
    const int b = bh >> 3, h = bh & 7;
    __shared__ float kvs[64][64];
    __shared__ float qsT[64][68];
    const int tid = threadIdx.x;

    const float4* kvsrc = (const float4*)(g_kv + (size_t)bh * (Dd * Dd));
    for (int i = tid; i < 1024; i += 256) ((float4*)kvs)[i] = kvsrc[i];

    const int lr = tid >> 3;
    const int lc = (tid & 7) << 3;
    const float* qb = g_q + (size_t)bh * Ntok * Dd + (size_t)(nt * 64) * Dd;
#pragma unroll
    for (int rr = lr; rr < 64; rr += 32) {
        float4 q0 = *(const float4*)(qb + rr * Dd + lc);
        float4 q1 = *(const float4*)(qb + rr * Dd + lc + 4);
        qsT[lc + 0][rr] = q0.x; qsT[lc + 1][rr] = q0.y;
        qsT[lc + 2][rr] = q0.z; qsT[lc + 3][rr] = q0.w;
        qsT[lc + 4][rr] = q1.x; qsT[lc + 5][rr] = q1.y;
        qsT[lc + 6][rr] = q1.z; qsT[lc + 7][rr] = q1.w;
    }
    __syncthreads();

    const int n0 = (tid & 15) << 2, e0 = (tid >> 4) << 2;
    float acc[4][4] = {};
#pragma unroll
    for (int d = 0; d < 64; d++) {
        float4 qa = *(const float4*)&qsT[d][n0];
        float4 kf = *(const float4*)&kvs[d][e0];
        float qr[4] = {qa.x, qa.y, qa.z, qa.w};
        float krr[4] = {kf.x, kf.y, kf.z, kf.w};
#pragma unroll
        for (int i = 0; i < 4; i++)
#pragma unroll
            for (int j = 0; j < 4; j++)
                acc[i][j] = fmaf(qr[i], krr[j], acc[i][j]);
    }

#pragma unroll
    for (int i = 0; i < 4; i++) {
        const int n = nt * 64 + n0 + i;
        const float scale = g_si[bh * Ntok + n] * g_sa[bh * Ntok + n];
        const int np = (h << 9) | (n >> 3);
        const int cbase = (n & 7) << 6;
        const size_t lin = (size_t)(b * Ntok + np) * Cc + cbase + e0;
#pragma unroll
        for (int j = 0; j < 4; j++) {
            float val = acc[i][j] * scale;
            __half hh = __float2half_rn(val);
            g_Ohi[lin + j] = hh;
            g_Olo[lin + j] = __float2half_rn(val - __half2float(hh));
        }
    }
}

// ---------------- launch ----------------
extern "C" void kernel_launch(void* const* d_in, const int* in_sizes, int n_in,
                              void* d_out, int out_size)
{
    const float* query = (const float*)d_in[0];
    const float* Wq = (const float*)d_in[1];
    const float* bq = (const float*)d_in[2];
    const float* Wk = (const float*)d_in[3];
    const float* bk = (const float*)d_in[4];
    const float* Wv = (const float*)d_in[5];
    const float* bv = (const float*)d_in[6];
    const float* Wo = (const float*)d_in[7];
    const float* bo = (const float*)d_in[8];
    const float* temp = (const float*)d_in[9];
    float* out = (float*)d_out;

    const int DSMEM = 3 * 32768 + 1024;
    cudaFuncSetAttribute(gemm_tc, cudaFuncAttributeMaxDynamicSharedMemorySize, DSMEM);

    __half *pAhi, *pAlo, *pOhi, *pOlo, *pB;
    cudaGetSymbolAddress((void**)&pAhi, g_Ahi);
    cudaGetSymbolAddress((void**)&pAlo, g_Alo);
    cudaGetSymbolAddress((void**)&pOhi, g_Ohi);
    cudaGetSymbolAddress((void**)&pOlo, g_Olo);
    cudaGetSymbolAddress((void**)&pB,  g_B);

    // operand conversion
    k_split<<<16384, 256>>>(query, pAhi, pAlo);
    k_convW<<<dim3(16, 16, 4), dim3(32, 8)>>>(Wq, Wk, Wv, Wo, pB);

    // q/k/v projections in one launch (z selects mode/weights)
    gemm_tc<<<dim3(4, 256, 3), 256, DSMEM>>>(pAhi, pAlo, pB, bq, bk, bv,
                                             nullptr, nullptr, 0);

    k_colsum<<<dim3(8, BH), 256>>>();
    k_red<<<(BH * Dd + 255) / 256, 256>>>(0);
    k_fuse1<<<dim3(8, BH), 256>>>();
    k_red<<<(BH * Dd + 255) / 256, 256>>>(1);
    k_conserved<<<(BH * Ntok) / 8, 256>>>();
    k_softmax<<<BH, 256>>>(temp);
    k_kv<<<dim3(8, BH), 256>>>();
    k_kvred<<<(BH * Dd * Dd + 255) / 256, 256>>>();
    k_outupd<<<dim3(64, BH), 256>>>();

    // output projection (+bias+residual)
    gemm_tc<<<dim3(4, 256, 1), 256, DSMEM>>>(pOhi, pOlo, pB + 3 * (512 * 1024), bo, bo, bo,
                                             query, out, 3);
}

// round 5
// speedup vs baseline: 4.3249x; 1.4805x over previous
#include <cuda_runtime.h>
#include <cuda_fp16.h>
#include <math.h>
#include <stdint.h>

#define Ntok 4096
#define Bb   8
#define Cc   512
#define Hh   8
#define Dd   64
#define BH   64          // B*H
#define EPSf 1e-6f
#define NCHUNK 8         // 512 K / 64 per chunk (single fp16 term)

// ---------------- scratch (static device arrays; no allocation) ----------------
__device__ __half g_qh[BH * Ntok * Dd];    // (B,H,N,D) sigmoid(q proj) fp16
__device__ __half g_kh[BH * Ntok * Dd];
__device__ __half g_vh[BH * Ntok * Dd];
__device__ float g_ksum[BH * Dd], g_qsum[BH * Dd];
__device__ float g_kso[BH * Dd],  g_qsi[BH * Dd];
__device__ float g_si[BH * Ntok], g_so[BH * Ntok];
__device__ float g_sa[BH * Ntok], g_cs[BH * Ntok], g_comp[BH * Ntok];
__device__ float g_kpart[8 * BH * Dd], g_qpart[8 * BH * Dd];
__device__ float g_kv[BH * Dd * Dd];
__device__ float g_kvpart[8 * BH * Dd * Dd];

// fp16 GEMM operands
__device__ __half g_Ah[32768 * 512];       // fp16(query)
__device__ __half g_Oh[32768 * 512];       // fp16(out_update), scrambled (B,N,C)
__device__ __half g_B[4 * 512 * 512];      // [proj][n][k]

// ---------------- PTX helpers (base-arch only) ----------------
__device__ __forceinline__ uint32_t smem_u32(const void* p) {
    uint32_t a;
    asm("{ .reg .u64 t; cvta.to.shared.u64 t, %1; cvt.u32.u64 %0, t; }" : "=r"(a) : "l"(p));
    return a;
}
__device__ __forceinline__ void cp16(uint32_t dst, const void* src) {
    asm volatile("cp.async.cg.shared.global [%0], [%1], 16;" :: "r"(dst), "l"(src) : "memory");
}
__device__ __forceinline__ void cp_commit() {
    asm volatile("cp.async.commit_group;" ::: "memory");
}
__device__ __forceinline__ void cp_wait2() {
    asm volatile("cp.async.wait_group 2;" ::: "memory");
}
__device__ __forceinline__ void ldm4(uint32_t* r, uint32_t addr) {
    asm volatile("ldmatrix.sync.aligned.m8n8.x4.shared.b16 {%0,%1,%2,%3}, [%4];"
                 : "=r"(r[0]), "=r"(r[1]), "=r"(r[2]), "=r"(r[3]) : "r"(addr));
}
__device__ __forceinline__ void mma16816(float* c, const uint32_t* a, const uint32_t* b) {
    asm volatile(
        "mma.sync.aligned.m16n8k16.row.col.f32.f16.f16.f32 "
        "{%0,%1,%2,%3}, {%4,%5,%6,%7}, {%8,%9}, {%0,%1,%2,%3};"
        : "+f"(c[0]), "+f"(c[1]), "+f"(c[2]), "+f"(c[3])
        : "r"(a[0]), "r"(a[1]), "r"(a[2]), "r"(a[3]), "r"(b[0]), "r"(b[1]));
}

// ---------------- conversion kernels ----------------
__global__ void k_split(const float* __restrict__ src, __half* __restrict__ dst)
{
    int i = blockIdx.x * blockDim.x + threadIdx.x;
    float4 v = ((const float4*)src)[i];
    __half2* hp = (__half2*)dst;
    hp[2 * i]     = __floats2half2_rn(v.x, v.y);
    hp[2 * i + 1] = __floats2half2_rn(v.z, v.w);
}

__global__ void k_convW(const float* __restrict__ Wq, const float* __restrict__ Wk,
                        const float* __restrict__ Wv, const float* __restrict__ Wo,
                        __half* __restrict__ Bop)
{
    const float* W = (blockIdx.z == 0) ? Wq : (blockIdx.z == 1) ? Wk
                   : (blockIdx.z == 2) ? Wv : Wo;
    __half* Bp = Bop + (size_t)blockIdx.z * (512 * 512);
    __shared__ float t[32][33];
    const int k0 = blockIdx.y * 32, n0 = blockIdx.x * 32;
    const int tx = threadIdx.x, ty = threadIdx.y;  // (32,8)
    for (int j = ty; j < 32; j += 8) t[j][tx] = W[(size_t)(k0 + j) * 512 + n0 + tx];
    __syncthreads();
    for (int j = ty; j < 32; j += 8)
        Bp[(size_t)(n0 + j) * 512 + (k0 + tx)] = __float2half_rn(t[tx][j]);
}

// ---------------- mma.sync GEMM: D[32768,512] = A[.,512] @ B^T ----------------
// mode 0: q (sigmoid -> g_qh), 1: k -> g_kh, 2: v -> g_vh, 3: out (+bias+resid -> d_out)
__global__ void __launch_bounds__(256) gemm_tc(
    const __half* __restrict__ A, const __half* __restrict__ Bbase,
    const float* __restrict__ b0, const float* __restrict__ b1, const float* __restrict__ b2,
    const float* __restrict__ resid, float* __restrict__ out, int modeBase)
{
    extern __shared__ char dyn[];
    const uint32_t sbase = (smem_u32(dyn) + 1023u) & ~1023u;
    const int tid = threadIdx.x;
    const int wid = tid >> 5, lane = tid & 31;
    const int bn = blockIdx.x * 128, bm = blockIdx.y * 128;
    const int mode = modeBase + blockIdx.z;
    const __half* Bop = Bbase + (size_t)blockIdx.z * (512 * 512);
    const float* bias = (mode == 1) ? b1 : (mode == 2) ? b2 : b0;
    const int warpM = wid & 3, warpN = wid >> 2;   // 4 x 2 warps -> 32x64 warp tile

    float acc[2][8][4];
#pragma unroll
    for (int mf = 0; mf < 2; mf++)
#pragma unroll
        for (int nf = 0; nf < 8; nf++)
#pragma unroll
            for (int i = 0; i < 4; i++) acc[mf][nf][i] = 0.f;

    int aRow[2], bRow[4];
#pragma unroll
    for (int mf = 0; mf < 2; mf++)
        aRow[mf] = warpM * 32 + mf * 16 + (lane & 7) + ((lane >> 3) & 1) * 8;
    const int aHi = lane >> 4;
#pragma unroll
    for (int nf2 = 0; nf2 < 4; nf2++)
        bRow[nf2] = warpN * 64 + nf2 * 16 + (lane & 7) + (lane >> 4) * 8;
    const int bHi = (lane >> 3) & 1;

    auto issue = [&](int c) {
        const int akoff = c << 6;
        const uint32_t buf = sbase + (uint32_t)(c % 3) * 32768u;
#pragma unroll
        for (int t = 0; t < 4; t++) {
            int s = tid + (t << 8);
            int row = s >> 3, sc = s & 7;
            uint32_t off = row * 128 + ((sc ^ (row & 7)) << 4);
            cp16(buf + off, A + ((size_t)(bm + row) * 512 + akoff + sc * 8));
        }
#pragma unroll
        for (int t = 0; t < 4; t++) {
            int s = tid + (t << 8);
            int row = s >> 3, sc = s & 7;
            uint32_t off = row * 128 + ((sc ^ (row & 7)) << 4);
            cp16(buf + 16384u + off, Bop + ((size_t)(bn + row) * 512 + akoff + sc * 8));
        }
    };

    issue(0); cp_commit();
    issue(1); cp_commit();

    for (int c = 0; c < NCHUNK; c++) {
        if (c + 2 < NCHUNK) issue(c + 2);
        cp_commit();
        cp_wait2();
        __syncthreads();

        const uint32_t abuf = sbase + (uint32_t)(c % 3) * 32768u;
        const uint32_t bbuf = abuf + 16384u;
#pragma unroll
        for (int ks = 0; ks < 4; ks++) {
            uint32_t a[2][4], b[4][4];
#pragma unroll
            for (int mf = 0; mf < 2; mf++) {
                const int row = aRow[mf];
                const int cc = 2 * ks + aHi;
                ldm4(a[mf], abuf + row * 128 + ((cc ^ (row & 7)) << 4));
            }
#pragma unroll
            for (int nf2 = 0; nf2 < 4; nf2++) {
                const int row = bRow[nf2];
                const int cc = 2 * ks + bHi;
                ldm4(b[nf2], bbuf + row * 128 + ((cc ^ (row & 7)) << 4));
            }
#pragma unroll
            for (int mf = 0; mf < 2; mf++)
#pragma unroll
                for (int nf = 0; nf < 8; nf++)
                    mma16816(acc[mf][nf], a[mf], &b[nf >> 1][(nf & 1) * 2]);
        }
        __syncthreads();
    }

    // ---------------- epilogue ----------------
    __half* dstg = (mode == 0) ? g_qh : (mode == 1) ? g_kh : g_vh;
    const int r0base = bm + warpM * 32 + (lane >> 2);
    const int cb = bn + warpN * 64 + ((lane & 3) << 1);
#pragma unroll
    for (int mf = 0; mf < 2; mf++)
#pragma unroll
        for (int half = 0; half < 2; half++) {
            const int r = r0base + mf * 16 + half * 8;
#pragma unroll
            for (int nf = 0; nf < 8; nf++) {
                const int c0 = cb + nf * 8;
                float2 v;
                v.x = acc[mf][nf][half * 2 + 0] + bias[c0];
                v.y = acc[mf][nf][half * 2 + 1] + bias[c0 + 1];
                if (mode <= 2) {
                    if (mode <= 1) {
                        v.x = 1.f / (1.f + expf(-v.x));
                        v.y = 1.f / (1.f + expf(-v.y));
                    }
                    const int n = r >> 3, bb = r & 7;
                    const int h = c0 >> 6, d = c0 & 63;
                    const size_t o = ((size_t)((bb << 3) | h) * Ntok + n) * Dd + d;
                    *(__half2*)(dstg + o) = __floats2half2_rn(v.x, v.y);
                } else {
                    const int bb = r >> 12, n = r & 4095;
                    const size_t o = (size_t)((n << 3) | bb) * Cc + c0;
                    float2 rs = *(const float2*)(resid + o);
                    v.x += rs.x; v.y += rs.y;
                    *(float2*)(out + o) = v;
                }
            }
        }
}

// ---------------- plain column sums over s (fp16 inputs, fp32 accum) ----------------
__global__ void k_colsum()
{
    const int bh = blockIdx.y, chunk = blockIdx.x;
    const int dp = threadIdx.x & 31, p = threadIdx.x >> 5;   // 32 d-pairs x 8 phases
    const __half* kb = g_kh + (size_t)bh * Ntok * Dd;
    const __half* qb = g_qh + (size_t)bh * Ntok * Dd;
    float ak0 = 0.f, ak1 = 0.f, aq0 = 0.f, aq1 = 0.f;
    const int s0 = chunk * 512;
    for (int s = s0 + p; s < s0 + 512; s += 8) {
        float2 kf = __half22float2(*(const __half2*)(kb + (size_t)s * Dd + 2 * dp));
        float2 qf = __half22float2(*(const __half2*)(qb + (size_t)s * Dd + 2 * dp));
        ak0 += kf.x; ak1 += kf.y;
        aq0 += qf.x; aq1 += qf.y;
    }
    __shared__ float sk[8][64], sq[8][64];
    sk[p][2 * dp] = ak0; sk[p][2 * dp + 1] = ak1;
    sq[p][2 * dp] = aq0; sq[p][2 * dp + 1] = aq1;
    __syncthreads();
    if (threadIdx.x < 64) {
        const int d = threadIdx.x;
        float a = 0.f, b = 0.f;
#pragma unroll
        for (int i = 0; i < 8; i++) { a += sk[i][d]; b += sq[i][d]; }
        g_kpart[(chunk * BH + bh) * Dd + d] = a;
        g_qpart[(chunk * BH + bh) * Dd + d] = b;
    }
}

__global__ void k_red(int mode)
{
    const int i = blockIdx.x * blockDim.x + threadIdx.x;
    if (i >= BH * Dd) return;
    float sk = 0.f, sq = 0.f;
#pragma unroll
    for (int c = 0; c < 8; c++) {
        sk += g_kpart[c * BH * Dd + i];
        sq += g_qpart[c * BH * Dd + i];
    }
    if (mode == 0) { g_ksum[i] = sk; g_qsum[i] = sq; }
    else           { g_kso[i]  = sk; g_qsi[i]  = sq; }
}

// ---------------- fused rownorm (si/so) + weighted colsum partials ----------------
__global__ void __launch_bounds__(256) k_fuse1()
{
    const int bh = blockIdx.y, chunk = blockIdx.x;
    const int w = threadIdx.x >> 5, lane = threadIdx.x & 31;
    const __half* qb = g_qh + (size_t)bh * Ntok * Dd;
    const __half* kb = g_kh + (size_t)bh * Ntok * Dd;
    const float ks0 = g_ksum[bh * Dd + 2 * lane] + EPSf;
    const float ks1 = g_ksum[bh * Dd + 2 * lane + 1] + EPSf;
    const float qs0 = g_qsum[bh * Dd + 2 * lane] + EPSf;
    const float qs1 = g_qsum[bh * Dd + 2 * lane + 1] + EPSf;
    float aq0 = 0.f, aq1 = 0.f, ak0 = 0.f, ak1 = 0.f;
    const int s0 = chunk * 512 + w * 64;
    for (int i = 0; i < 64; i++) {
        const int s = s0 + i;
        float2 qf = __half22float2(*(const __half2*)(qb + (size_t)s * Dd + 2 * lane));
        float2 kf = __half22float2(*(const __half2*)(kb + (size_t)s * Dd + 2 * lane));
        float s1 = (qf.x + EPSf) * ks0 + (qf.y + EPSf) * ks1;
        float s2 = (kf.x + EPSf) * qs0 + (kf.y + EPSf) * qs1;
#pragma unroll
        for (int o = 16; o > 0; o >>= 1) {
            s1 += __shfl_xor_sync(0xffffffffu, s1, o);
            s2 += __shfl_xor_sync(0xffffffffu, s2, o);
        }
        const float si = 1.f / (s1 + EPSf);
        const float so = 1.f / (s2 + EPSf);
        if (lane == 0) { g_si[bh * Ntok + s] = si; g_so[bh * Ntok + s] = so; }
        aq0 += si * qf.x; aq1 += si * qf.y;
        ak0 += so * kf.x; ak1 += so * kf.y;
    }
    __shared__ float sQ[8][64], sK[8][64];
    sQ[w][2 * lane] = aq0; sQ[w][2 * lane + 1] = aq1;
    sK[w][2 * lane] = ak0; sK[w][2 * lane + 1] = ak1;
    __syncthreads();
    if (threadIdx.x < 64) {
        const int d = threadIdx.x;
        float sq = 0.f, sk = 0.f;
#pragma unroll
        for (int w2 = 0; w2 < 8; w2++) { sq += sQ[w2][d]; sk += sK[w2][d]; }
        g_qpart[(chunk * BH + bh) * Dd + d] = sq;   // si-weighted q sums
        g_kpart[(chunk * BH + bh) * Dd + d] = sk;   // so-weighted k sums
    }
}

__global__ void k_conserved()
{
    const int w = (blockIdx.x * blockDim.x + threadIdx.x) >> 5;
    const int lane = threadIdx.x & 31;
    const int bh = w >> 12;
    const __half* qr = g_qh + (size_t)w * Dd;
    const __half* kr = g_kh + (size_t)w * Dd;
    const float* kso = g_kso + bh * Dd;
    const float* qsi = g_qsi + bh * Dd;
    float2 qf = __half22float2(*(const __half2*)(qr + 2 * lane));
    float2 kf = __half22float2(*(const __half2*)(kr + 2 * lane));
    float s1 = (qf.x + EPSf) * (kso[2 * lane] + EPSf)
             + (qf.y + EPSf) * (kso[2 * lane + 1] + EPSf);
    float s2 = (kf.x + EPSf) * (qsi[2 * lane] + EPSf)
             + (kf.y + EPSf) * (qsi[2 * lane + 1] + EPSf);
#pragma unroll
    for (int o = 16; o > 0; o >>= 1) {
        s1 += __shfl_xor_sync(0xffffffffu, s1, o);
        s2 += __shfl_xor_sync(0xffffffffu, s2, o);
    }
    if (lane == 0) {
        float cs_sink = s1 + EPSf;
        g_sa[w] = 1.f / (1.f + expf(-cs_sink));
        float cs_src = s2 + EPSf;
        g_cs[w] = fminf(1.f, fmaxf(-1.f, cs_src));
    }
}

__global__ void k_softmax(const float* __restrict__ tptr)
{
    const int bh = blockIdx.x, t = threadIdx.x;
    const float* cs = g_cs + bh * Ntok;
    const float invT = 1.f / tptr[0];
    float v[16];
    float lmax = -3.4e38f;
#pragma unroll
    for (int i = 0; i < 16; i++) {
        v[i] = cs[t + (i << 8)];
        lmax = fmaxf(lmax, v[i]);
    }
    __shared__ float red[256];
    red[t] = lmax; __syncthreads();
    for (int o = 128; o > 0; o >>= 1) { if (t < o) red[t] = fmaxf(red[t], red[t + o]); __syncthreads(); }
    const float mx = red[0];
    __syncthreads();
    float lsum = 0.f;
#pragma unroll
    for (int i = 0; i < 16; i++) { v[i] = expf((v[i] - mx) * invT); lsum += v[i]; }
    red[t] = lsum; __syncthreads();
    for (int o = 128; o > 0; o >>= 1) { if (t < o) red[t] += red[t + o]; __syncthreads(); }
    const float scale = (float)Cc / red[0];
#pragma unroll
    for (int i = 0; i < 16; i++) g_comp[bh * Ntok + t + (i << 8)] = v[i] * scale;
}

__global__ void __launch_bounds__(256) k_kv()
{
    const int bh = blockIdx.y, chunk = blockIdx.x;
    __shared__ float ks[32][64];
    __shared__ float ws[32][64];
    const int tid = threadIdx.x;
    const int lr = tid >> 3;
    const int lc = (tid & 7) << 3;
    const size_t base = (size_t)bh * Ntok * Dd;
    const int d0 = (tid & 15) << 2, e0 = (tid >> 4) << 2;
    float acc[4][4] = {};
    for (int s0 = chunk * 512; s0 < chunk * 512 + 512; s0 += 32) {
        const int s = s0 + lr;
        const float cmp = g_comp[bh * Ntok + s];
        uint4 kraw = *(const uint4*)(g_kh + base + (size_t)s * Dd + lc);
        uint4 vraw = *(const uint4*)(g_vh + base + (size_t)s * Dd + lc);
        const __half2* kh2 = (const __half2*)&kraw;
        const __half2* vh2 = (const __half2*)&vraw;
#pragma unroll
        for (int j = 0; j < 4; j++) {
            float2 kf = __half22float2(kh2[j]);
            float2 vf = __half22float2(vh2[j]);
            ks[lr][lc + 2 * j]     = kf.x;
            ks[lr][lc + 2 * j + 1] = kf.y;
            ws[lr][lc + 2 * j]     = vf.x * cmp;
            ws[lr][lc + 2 * j + 1] = vf.y * cmp;
        }
        __syncthreads();
#pragma unroll
        for (int ss = 0; ss < 32; ss++) {
            float4 kf = *(const float4*)&ks[ss][d0];
            float4 wf = *(const float4*)&ws[ss][e0];
            float krr[4] = {kf.x, kf.y, kf.z, kf.w};
            float wr[4] = {wf.x, wf.y, wf.z, wf.w};
#pragma unroll
            for (int i = 0; i < 4; i++)
#pragma unroll
                for (int j = 0; j < 4; j++)
                    acc[i][j] = fmaf(krr[i], wr[j], acc[i][j]);
        }
        __syncthreads();
    }
    float* dst = g_kvpart + ((size_t)chunk * BH + bh) * Dd * Dd;
#pragma unroll
    for (int i = 0; i < 4; i++)
#pragma unroll
        for (int j = 0; j < 4; j++)
            dst[(d0 + i) * Dd + e0 + j] = acc[i][j];
}

__global__ void k_kvred()
{
    const int i = blockIdx.x * blockDim.x + threadIdx.x;
    if (i >= BH * Dd * Dd) return;
    float s = 0.f;
#pragma unroll
    for (int c = 0; c < 8; c++) s += g_kvpart[(size_t)c * BH * Dd * Dd + i];
    g_kv[i] = s;
}

// ---------------- out_update = (q @ kv) * si * sa -> fp16 scrambled (B,N,C) ----------------
__global__ void __launch_bounds__(256) k_outupd()
{
    const int bh = blockIdx.y, nt = blockIdx.x;
    const int b = bh >> 3, h = bh & 7;
    __shared__ float kvs[64][64];
    __shared__ float qsT[64][68];
    const int tid = threadIdx.x;

    const float4* kvsrc = (const float4*)(g_kv + (size_t)bh * (Dd * Dd));
    for (int i = tid; i < 1024; i += 256) ((float4*)kvs)[i] = kvsrc[i];

    const int lr = tid >> 3;
    const int lc = (tid & 7) << 3;
    const __half* qb = g_qh + (size_t)bh * Ntok * Dd + (size_t)(nt * 64) * Dd;
#pragma unroll
    for (int rr = lr; rr < 64; rr += 32) {
        uint4 qraw = *(const uint4*)(qb + rr * Dd + lc);
        const __half2* qh2 = (const __half2*)&qraw;
#pragma unroll
        for (int j = 0; j < 4; j++) {
            float2 qf = __half22float2(qh2[j]);
            qsT[lc + 2 * j][rr]     = qf.x;
            qsT[lc + 2 * j + 1][rr] = qf.y;
        }
    }
    __syncthreads();

    const int n0 = (tid & 15) << 2, e0 = (tid >> 4) << 2;
    float acc[4][4] = {};
#pragma unroll
    for (int d = 0; d < 64; d++) {
        float4 qa = *(const float4*)&qsT[d][n0];
        float4 kf = *(const float4*)&kvs[d][e0];
        float qr[4] = {qa.x, qa.y, qa.z, qa.w};
        float krr[4] = {kf.x, kf.y, kf.z, kf.w};
#pragma unroll
        for (int i = 0; i < 4; i++)
#pragma unroll
            for (int j = 0; j < 4; j++)
                acc[i][j] = fmaf(qr[i], krr[j], acc[i][j]);
    }

#pragma unroll
    for (int i = 0; i < 4; i++) {
        const int n = nt * 64 + n0 + i;
        const float scale = g_si[bh * Ntok + n] * g_sa[bh * Ntok + n];
        const int np = (h << 9) | (n >> 3);
        const int cbase = (n & 7) << 6;
        const size_t lin = (size_t)(b * Ntok + np) * Cc + cbase + e0;
        __half2 h01 = __floats2half2_rn(acc[i][0] * scale, acc[i][1] * scale);
        __half2 h23 = __floats2half2_rn(acc[i][2] * scale, acc[i][3] * scale);
        *(__half2*)(g_Oh + lin)     = h01;
        *(__half2*)(g_Oh + lin + 2) = h23;
    }
}

// ---------------- launch ----------------
extern "C" void kernel_launch(void* const* d_in, const int* in_sizes, int n_in,
                              void* d_out, int out_size)
{
    const float* query = (const float*)d_in[0];
    const float* Wq = (const float*)d_in[1];
    const float* bq = (const float*)d_in[2];
    const float* Wk = (const float*)d_in[3];
    const float* bk = (const float*)d_in[4];
    const float* Wv = (const float*)d_in[5];
    const float* bv = (const float*)d_in[6];
    const float* Wo = (const float*)d_in[7];
    const float* bo = (const float*)d_in[8];
    const float* temp = (const float*)d_in[9];
    float* out = (float*)d_out;

    const int DSMEM = 3 * 32768 + 1024;
    cudaFuncSetAttribute(gemm_tc, cudaFuncAttributeMaxDynamicSharedMemorySize, DSMEM);

    __half *pAh, *pOh, *pB;
    cudaGetSymbolAddress((void**)&pAh, g_Ah);
    cudaGetSymbolAddress((void**)&pOh, g_Oh);
    cudaGetSymbolAddress((void**)&pB,  g_B);

    // operand conversion
    k_split<<<16384, 256>>>(query, pAh);
    k_convW<<<dim3(16, 16, 4), dim3(32, 8)>>>(Wq, Wk, Wv, Wo, pB);

    // q/k/v projections in one launch (z selects mode/weights)
    gemm_tc<<<dim3(4, 256, 3), 256, DSMEM>>>(pAh, pB, bq, bk, bv, nullptr, nullptr, 0);

    k_colsum<<<dim3(8, BH), 256>>>();
    k_red<<<(BH * Dd + 255) / 256, 256>>>(0);
    k_fuse1<<<dim3(8, BH), 256>>>();
    k_red<<<(BH * Dd + 255) / 256, 256>>>(1);
    k_conserved<<<(BH * Ntok) / 8, 256>>>();
    k_softmax<<<BH, 256>>>(temp);
    k_kv<<<dim3(8, BH), 256>>>();
    k_kvred<<<(BH * Dd * Dd + 255) / 256, 256>>>();
    k_outupd<<<dim3(64, BH), 256>>>();

    // output projection (+bias+residual)
    gemm_tc<<<dim3(4, 256, 1), 256, DSMEM>>>(pOh, pB + 3 * (512 * 512), bo, bo, bo,
                                             query, out, 3);
}

// round 6
// speedup vs baseline: 4.7584x; 1.1002x over previous
#include <cuda_runtime.h>
#include <cuda_fp16.h>
#include <math.h>
#include <stdint.h>

#define Ntok 4096
#define Bb   8
#define Cc   512
#define Hh   8
#define Dd   64
#define BH   64          // B*H
#define EPSf 1e-6f
#define NCHUNK 8         // 512 K / 64 per chunk
#define MCH   16         // mid-section chunks

// ---------------- scratch (static device arrays; no allocation) ----------------
__device__ __half g_qh[BH * Ntok * Dd];    // (B,H,N,D) sigmoid(q proj) fp16
__device__ __half g_kh[BH * Ntok * Dd];
__device__ __half g_vh[BH * Ntok * Dd];
__device__ float g_si[BH * Ntok], g_so[BH * Ntok];
__device__ float g_sa[BH * Ntok], g_cs[BH * Ntok], g_comp[BH * Ntok];
__device__ float g_kpart[MCH * BH * Dd],  g_qpart[MCH * BH * Dd];   // plain col sums
__device__ float g_kpart2[MCH * BH * Dd], g_qpart2[MCH * BH * Dd];  // weighted col sums
__device__ float g_kv[BH * Dd * Dd];
__device__ float g_kvpart[MCH * BH * Dd * Dd];

// fp16 GEMM operands
__device__ __half g_Ah[32768 * 512];       // fp16(query)
__device__ __half g_Oh[32768 * 512];       // fp16(out_update), scrambled (B,N,C)
__device__ __half g_B[4 * 512 * 512];      // [proj][n][k]

// ---------------- PTX helpers (base-arch only) ----------------
__device__ __forceinline__ uint32_t smem_u32(const void* p) {
    uint32_t a;
    asm("{ .reg .u64 t; cvta.to.shared.u64 t, %1; cvt.u32.u64 %0, t; }" : "=r"(a) : "l"(p));
    return a;
}
__device__ __forceinline__ void cp16(uint32_t dst, const void* src) {
    asm volatile("cp.async.cg.shared.global [%0], [%1], 16;" :: "r"(dst), "l"(src) : "memory");
}
__device__ __forceinline__ void cp_commit() {
    asm volatile("cp.async.commit_group;" ::: "memory");
}
__device__ __forceinline__ void cp_wait2() {
    asm volatile("cp.async.wait_group 2;" ::: "memory");
}
__device__ __forceinline__ void ldm4(uint32_t* r, uint32_t addr) {
    asm volatile("ldmatrix.sync.aligned.m8n8.x4.shared.b16 {%0,%1,%2,%3}, [%4];"
                 : "=r"(r[0]), "=r"(r[1]), "=r"(r[2]), "=r"(r[3]) : "r"(addr));
}
__device__ __forceinline__ void mma16816(float* c, const uint32_t* a, const uint32_t* b) {
    asm volatile(
        "mma.sync.aligned.m16n8k16.row.col.f32.f16.f16.f32 "
        "{%0,%1,%2,%3}, {%4,%5,%6,%7}, {%8,%9}, {%0,%1,%2,%3};"
        : "+f"(c[0]), "+f"(c[1]), "+f"(c[2]), "+f"(c[3])
        : "r"(a[0]), "r"(a[1]), "r"(a[2]), "r"(a[3]), "r"(b[0]), "r"(b[1]));
}

// ---------------- conversion kernels ----------------
__global__ void k_split(const float* __restrict__ src, __half* __restrict__ dst)
{
    int i = blockIdx.x * blockDim.x + threadIdx.x;
    float4 v = ((const float4*)src)[i];
    __half2* hp = (__half2*)dst;
    hp[2 * i]     = __floats2half2_rn(v.x, v.y);
    hp[2 * i + 1] = __floats2half2_rn(v.z, v.w);
}

__global__ void k_convW(const float* __restrict__ Wq, const float* __restrict__ Wk,
                        const float* __restrict__ Wv, const float* __restrict__ Wo,
                        __half* __restrict__ Bop)
{
    const float* W = (blockIdx.z == 0) ? Wq : (blockIdx.z == 1) ? Wk
                   : (blockIdx.z == 2) ? Wv : Wo;
    __half* Bp = Bop + (size_t)blockIdx.z * (512 * 512);
    __shared__ float t[32][33];
    const int k0 = blockIdx.y * 32, n0 = blockIdx.x * 32;
    const int tx = threadIdx.x, ty = threadIdx.y;  // (32,8)
    for (int j = ty; j < 32; j += 8) t[j][tx] = W[(size_t)(k0 + j) * 512 + n0 + tx];
    __syncthreads();
    for (int j = ty; j < 32; j += 8)
        Bp[(size_t)(n0 + j) * 512 + (k0 + tx)] = __float2half_rn(t[tx][j]);
}

// ---------------- mma.sync GEMM: D[32768,512] = A[.,512] @ B^T ----------------
// mode 0: q (sigmoid -> g_qh), 1: k -> g_kh, 2: v -> g_vh, 3: out (+bias+resid -> d_out)
__global__ void __launch_bounds__(256) gemm_tc(
    const __half* __restrict__ A, const __half* __restrict__ Bbase,
    const float* __restrict__ b0, const float* __restrict__ b1, const float* __restrict__ b2,
    const float* __restrict__ resid, float* __restrict__ out, int modeBase)
{
    extern __shared__ char dyn[];
    const uint32_t sbase = (smem_u32(dyn) + 1023u) & ~1023u;
    char* dynA = dyn + (sbase - smem_u32(dyn));   // C++ pointer to aligned base
    const int tid = threadIdx.x;
    const int wid = tid >> 5, lane = tid & 31;
    const int bn = blockIdx.x * 128, bm = blockIdx.y * 128;
    const int mode = modeBase + blockIdx.z;
    const __half* Bop = Bbase + (size_t)blockIdx.z * (512 * 512);
    const float* bias = (mode == 1) ? b1 : (mode == 2) ? b2 : b0;
    const int warpM = wid & 3, warpN = wid >> 2;   // 4 x 2 warps -> 32x64 warp tile

    float acc[2][8][4];
#pragma unroll
    for (int mf = 0; mf < 2; mf++)
#pragma unroll
        for (int nf = 0; nf < 8; nf++)
#pragma unroll
            for (int i = 0; i < 4; i++) acc[mf][nf][i] = 0.f;

    int aRow[2], bRow[4];
#pragma unroll
    for (int mf = 0; mf < 2; mf++)
        aRow[mf] = warpM * 32 + mf * 16 + (lane & 7) + ((lane >> 3) & 1) * 8;
    const int aHi = lane >> 4;
#pragma unroll
    for (int nf2 = 0; nf2 < 4; nf2++)
        bRow[nf2] = warpN * 64 + nf2 * 16 + (lane & 7) + (lane >> 4) * 8;
    const int bHi = (lane >> 3) & 1;

    auto issue = [&](int c) {
        const int akoff = c << 6;
        const uint32_t buf = sbase + (uint32_t)(c % 3) * 32768u;
#pragma unroll
        for (int t = 0; t < 4; t++) {
            int s = tid + (t << 8);
            int row = s >> 3, sc = s & 7;
            uint32_t off = row * 128 + ((sc ^ (row & 7)) << 4);
            cp16(buf + off, A + ((size_t)(bm + row) * 512 + akoff + sc * 8));
        }
#pragma unroll
        for (int t = 0; t < 4; t++) {
            int s = tid + (t << 8);
            int row = s >> 3, sc = s & 7;
            uint32_t off = row * 128 + ((sc ^ (row & 7)) << 4);
            cp16(buf + 16384u + off, Bop + ((size_t)(bn + row) * 512 + akoff + sc * 8));
        }
    };

    issue(0); cp_commit();
    issue(1); cp_commit();

    for (int c = 0; c < NCHUNK; c++) {
        if (c + 2 < NCHUNK) issue(c + 2);
        cp_commit();
        cp_wait2();
        __syncthreads();

        const uint32_t abuf = sbase + (uint32_t)(c % 3) * 32768u;
        const uint32_t bbuf = abuf + 16384u;
#pragma unroll
        for (int ks = 0; ks < 4; ks++) {
            uint32_t a[2][4], b[4][4];
#pragma unroll
            for (int mf = 0; mf < 2; mf++) {
                const int row = aRow[mf];
                const int cc = 2 * ks + aHi;
                ldm4(a[mf], abuf + row * 128 + ((cc ^ (row & 7)) << 4));
            }
#pragma unroll
            for (int nf2 = 0; nf2 < 4; nf2++) {
                const int row = bRow[nf2];
                const int cc = 2 * ks + bHi;
                ldm4(b[nf2], bbuf + row * 128 + ((cc ^ (row & 7)) << 4));
            }
#pragma unroll
            for (int mf = 0; mf < 2; mf++)
#pragma unroll
                for (int nf = 0; nf < 8; nf++)
                    mma16816(acc[mf][nf], a[mf], &b[nf >> 1][(nf & 1) * 2]);
        }
        __syncthreads();
    }

    // ---------------- epilogue ----------------
    if (mode <= 2) {
        // stage fp16 tile in smem (pitch 136 halves: conflict-free), then
        // emit fully-coalesced 16B/lane stores to (B,H,N,D) layout.
        __half* smh = (__half*)dynA;
        const int rloc = warpM * 32 + (lane >> 2);
        const int cloc = warpN * 64 + ((lane & 3) << 1);
#pragma unroll
        for (int mf = 0; mf < 2; mf++)
#pragma unroll
            for (int half = 0; half < 2; half++) {
#pragma unroll
                for (int nf = 0; nf < 8; nf++) {
                    const int c0 = bn + cloc + nf * 8;
                    float vx = acc[mf][nf][half * 2 + 0] + bias[c0];
                    float vy = acc[mf][nf][half * 2 + 1] + bias[c0 + 1];
                    if (mode <= 1) {
                        vx = 1.f / (1.f + expf(-vx));
                        vy = 1.f / (1.f + expf(-vy));
                    }
                    *(__half2*)&smh[(rloc + mf * 16 + half * 8) * 136 + cloc + nf * 8]
                        = __floats2half2_rn(vx, vy);
                }
            }
        __syncthreads();
        __half* dstg = (mode == 0) ? g_qh : (mode == 1) ? g_kh : g_vh;
        const int h0 = bn >> 6;
        const int hl = tid >> 7, nl = (tid & 127) >> 3, dp = tid & 7;
#pragma unroll
        for (int bb2 = 0; bb2 < 8; bb2++) {
            uint4 val = *(const uint4*)(smh + (size_t)(nl * 8 + bb2) * 136 + hl * 64 + dp * 8);
            *(uint4*)(dstg + ((size_t)((bb2 << 3) | (h0 + hl)) * Ntok + (bm >> 3) + nl) * Dd + dp * 8) = val;
        }
    } else {
        const int r0base = bm + warpM * 32 + (lane >> 2);
        const int cb = bn + warpN * 64 + ((lane & 3) << 1);
#pragma unroll
        for (int mf = 0; mf < 2; mf++)
#pragma unroll
            for (int half = 0; half < 2; half++) {
                const int r = r0base + mf * 16 + half * 8;
#pragma unroll
                for (int nf = 0; nf < 8; nf++) {
                    const int c0 = cb + nf * 8;
                    const int bb = r >> 12, n = r & 4095;
                    const size_t o = (size_t)((n << 3) | bb) * Cc + c0;
                    float2 rs = *(const float2*)(resid + o);
                    float2 v;
                    v.x = acc[mf][nf][half * 2 + 0] + bias[c0] + rs.x;
                    v.y = acc[mf][nf][half * 2 + 1] + bias[c0 + 1] + rs.y;
                    *(float2*)(out + o) = v;
                }
            }
    }
}

// ---------------- plain column sums over s (fp16 inputs, fp32 accum) ----------------
__global__ void k_colsum()
{
    const int bh = blockIdx.y, chunk = blockIdx.x;
    const int dp = threadIdx.x & 31, p = threadIdx.x >> 5;   // 32 d-pairs x 8 phases
    const __half* kb = g_kh + (size_t)bh * Ntok * Dd;
    const __half* qb = g_qh + (size_t)bh * Ntok * Dd;
    float ak0 = 0.f, ak1 = 0.f, aq0 = 0.f, aq1 = 0.f;
    const int s0 = chunk * 256;
    for (int s = s0 + p; s < s0 + 256; s += 8) {
        float2 kf = __half22float2(*(const __half2*)(kb + (size_t)s * Dd + 2 * dp));
        float2 qf = __half22float2(*(const __half2*)(qb + (size_t)s * Dd + 2 * dp));
        ak0 += kf.x; ak1 += kf.y;
        aq0 += qf.x; aq1 += qf.y;
    }
    __shared__ float sk[8][64], sq[8][64];
    sk[p][2 * dp] = ak0; sk[p][2 * dp + 1] = ak1;
    sq[p][2 * dp] = aq0; sq[p][2 * dp + 1] = aq1;
    __syncthreads();
    if (threadIdx.x < 64) {
        const int d = threadIdx.x;
        float a = 0.f, b = 0.f;
#pragma unroll
        for (int i = 0; i < 8; i++) { a += sk[i][d]; b += sq[i][d]; }
        g_kpart[(chunk * BH + bh) * Dd + d] = a;
        g_qpart[(chunk * BH + bh) * Dd + d] = b;
    }
}

// ---------------- fused: reduce colsum partials + rownorm (si/so) + weighted colsums ----------------
__global__ void __launch_bounds__(256) k_fuse1()
{
    const int bh = blockIdx.y, chunk = blockIdx.x;
    const int w = threadIdx.x >> 5, lane = threadIdx.x & 31;
    __shared__ float ksS[64], qsS[64];
    __shared__ float sQ[8][64], sK[8][64];
    if (threadIdx.x < 64) {
        float a = 0.f, b = 0.f;
#pragma unroll
        for (int c = 0; c < MCH; c++) {
            a += g_kpart[(c * BH + bh) * Dd + threadIdx.x];
            b += g_qpart[(c * BH + bh) * Dd + threadIdx.x];
        }
        ksS[threadIdx.x] = a + EPSf;
        qsS[threadIdx.x] = b + EPSf;
    }
    __syncthreads();
    const __half* qb = g_qh + (size_t)bh * Ntok * Dd;
    const __half* kb = g_kh + (size_t)bh * Ntok * Dd;
    const float ks0 = ksS[2 * lane], ks1 = ksS[2 * lane + 1];
    const float qs0 = qsS[2 * lane], qs1 = qsS[2 * lane + 1];
    float aq0 = 0.f, aq1 = 0.f, ak0 = 0.f, ak1 = 0.f;
    const int s0 = chunk * 256 + w * 32;
    for (int i = 0; i < 32; i++) {
        const int s = s0 + i;
        float2 qf = __half22float2(*(const __half2*)(qb + (size_t)s * Dd + 2 * lane));
        float2 kf = __half22float2(*(const __half2*)(kb + (size_t)s * Dd + 2 * lane));
        float s1 = (qf.x + EPSf) * ks0 + (qf.y + EPSf) * ks1;
        float s2 = (kf.x + EPSf) * qs0 + (kf.y + EPSf) * qs1;
#pragma unroll
        for (int o = 16; o > 0; o >>= 1) {
            s1 += __shfl_xor_sync(0xffffffffu, s1, o);
            s2 += __shfl_xor_sync(0xffffffffu, s2, o);
        }
        const float si = 1.f / (s1 + EPSf);
        const float so = 1.f / (s2 + EPSf);
        if (lane == 0) { g_si[bh * Ntok + s] = si; g_so[bh * Ntok + s] = so; }
        aq0 += si * qf.x; aq1 += si * qf.y;
        ak0 += so * kf.x; ak1 += so * kf.y;
    }
    sQ[w][2 * lane] = aq0; sQ[w][2 * lane + 1] = aq1;
    sK[w][2 * lane] = ak0; sK[w][2 * lane + 1] = ak1;
    __syncthreads();
    if (threadIdx.x < 64) {
        const int d = threadIdx.x;
        float sq = 0.f, sk = 0.f;
#pragma unroll
        for (int w2 = 0; w2 < 8; w2++) { sq += sQ[w2][d]; sk += sK[w2][d]; }
        g_qpart2[(chunk * BH + bh) * Dd + d] = sq;   // si-weighted q sums -> qsi
        g_kpart2[(chunk * BH + bh) * Dd + d] = sk;   // so-weighted k sums -> kso
    }
}

// ---------------- fused: reduce weighted partials + conserved sink/source ----------------
__global__ void __launch_bounds__(256) k_conserved()
{
    const int bh = blockIdx.y, chunk = blockIdx.x;
    const int w = threadIdx.x >> 5, lane = threadIdx.x & 31;
    __shared__ float koS[64], qiS[64];
    if (threadIdx.x < 64) {
        float a = 0.f, b = 0.f;
#pragma unroll
        for (int c = 0; c < MCH; c++) {
            a += g_kpart2[(c * BH + bh) * Dd + threadIdx.x];
            b += g_qpart2[(c * BH + bh) * Dd + threadIdx.x];
        }
        koS[threadIdx.x] = a + EPSf;   // kso + eps
        qiS[threadIdx.x] = b + EPSf;   // qsi + eps
    }
    __syncthreads();
    const __half* qb = g_qh + (size_t)bh * Ntok * Dd;
    const __half* kb = g_kh + (size_t)bh * Ntok * Dd;
    const float ko0 = koS[2 * lane], ko1 = koS[2 * lane + 1];
    const float qi0 = qiS[2 * lane], qi1 = qiS[2 * lane + 1];
    const int s0 = chunk * 256 + w * 32;
    for (int i = 0; i < 32; i++) {
        const int s = s0 + i;
        float2 qf = __half22float2(*(const __half2*)(qb + (size_t)s * Dd + 2 * lane));
        float2 kf = __half22float2(*(const __half2*)(kb + (size_t)s * Dd + 2 * lane));
        float s1 = (qf.x + EPSf) * ko0 + (qf.y + EPSf) * ko1;
        float s2 = (kf.x + EPSf) * qi0 + (kf.y + EPSf) * qi1;
#pragma unroll
        for (int o = 16; o > 0; o >>= 1) {
            s1 += __shfl_xor_sync(0xffffffffu, s1, o);
            s2 += __shfl_xor_sync(0xffffffffu, s2, o);
        }
        if (lane == 0) {
            const float cs_sink = s1 + EPSf;
            g_sa[bh * Ntok + s] = 1.f / (1.f + expf(-cs_sink));
            const float cs_src = s2 + EPSf;
            g_cs[bh * Ntok + s] = fminf(1.f, fmaxf(-1.f, cs_src));
        }
    }
}

__global__ void k_softmax(const float* __restrict__ tptr)
{
    const int bh = blockIdx.x, t = threadIdx.x;
    const float* cs = g_cs + bh * Ntok;
    const float invT = 1.f / tptr[0];
    float v[16];
    float lmax = -3.4e38f;
#pragma unroll
    for (int i = 0; i < 16; i++) {
        v[i] = cs[t + (i << 8)];
        lmax = fmaxf(lmax, v[i]);
    }
    __shared__ float red[256];
    red[t] = lmax; __syncthreads();
    for (int o = 128; o > 0; o >>= 1) { if (t < o) red[t] = fmaxf(red[t], red[t + o]); __syncthreads(); }
    const float mx = red[0];
    __syncthreads();
    float lsum = 0.f;
#pragma unroll
    for (int i = 0; i < 16; i++) { v[i] = expf((v[i] - mx) * invT); lsum += v[i]; }
    red[t] = lsum; __syncthreads();
    for (int o = 128; o > 0; o >>= 1) { if (t < o) red[t] += red[t + o]; __syncthreads(); }
    const float scale = (float)Cc / red[0];
#pragma unroll
    for (int i = 0; i < 16; i++) g_comp[bh * Ntok + t + (i << 8)] = v[i] * scale;
}

__global__ void __launch_bounds__(256) k_kv()
{
    const int bh = blockIdx.y, chunk = blockIdx.x;
    __shared__ float ks[32][64];
    __shared__ float ws[32][64];
    const int tid = threadIdx.x;
    const int lr = tid >> 3;
    const int lc = (tid & 7) << 3;
    const size_t base = (size_t)bh * Ntok * Dd;
    const int d0 = (tid & 15) << 2, e0 = (tid >> 4) << 2;
    float acc[4][4] = {};
    for (int s0 = chunk * 256; s0 < chunk * 256 + 256; s0 += 32) {
        const int s = s0 + lr;
        const float cmp = g_comp[bh * Ntok + s];
        uint4 kraw = *(const uint4*)(g_kh + base + (size_t)s * Dd + lc);
        uint4 vraw = *(const uint4*)(g_vh + base + (size_t)s * Dd + lc);
        const __half2* kh2 = (const __half2*)&kraw;
        const __half2* vh2 = (const __half2*)&vraw;
#pragma unroll
        for (int j = 0; j < 4; j++) {
            float2 kf = __half22float2(kh2[j]);
            float2 vf = __half22float2(vh2[j]);
            ks[lr][lc + 2 * j]     = kf.x;
            ks[lr][lc + 2 * j + 1] = kf.y;
            ws[lr][lc + 2 * j]     = vf.x * cmp;
            ws[lr][lc + 2 * j + 1] = vf.y * cmp;
        }
        __syncthreads();
#pragma unroll
        for (int ss = 0; ss < 32; ss++) {
            float4 kf = *(const float4*)&ks[ss][d0];
            float4 wf = *(const float4*)&ws[ss][e0];
            float krr[4] = {kf.x, kf.y, kf.z, kf.w};
            float wr[4] = {wf.x, wf.y, wf.z, wf.w};
#pragma unroll
            for (int i = 0; i < 4; i++)
#pragma unroll
                for (int j = 0; j < 4; j++)
                    acc[i][j] = fmaf(krr[i], wr[j], acc[i][j]);
        }
        __syncthreads();
    }
    float* dst = g_kvpart + ((size_t)chunk * BH + bh) * Dd * Dd;
#pragma unroll
    for (int i = 0; i < 4; i++)
#pragma unroll
        for (int j = 0; j < 4; j++)
            dst[(d0 + i) * Dd + e0 + j] = acc[i][j];
}

__global__ void k_kvred()
{
    const int i = blockIdx.x * blockDim.x + threadIdx.x;
    if (i >= BH * Dd * Dd) return;
    float s = 0.f;
#pragma unroll
    for (int c = 0; c < MCH; c++) s += g_kvpart[(size_t)c * BH * Dd * Dd + i];
    g_kv[i] = s;
}

// ---------------- out_update = (q @ kv) * si * sa -> fp16 scrambled (B,N,C) ----------------
__global__ void __launch_bounds__(256) k_outupd()
{
    const int bh = blockIdx.y, nt = blockIdx.x;
    const int b = bh >> 3, h = bh & 7;
    __shared__ float kvs[64][64];
    __shared__ float qsT[64][68];
    const int tid = threadIdx.x;

    const float4* kvsrc = (const float4*)(g_kv + (size_t)bh * (Dd * Dd));
    for (int i = tid; i < 1024; i += 256) ((float4*)kvs)[i] = kvsrc[i];

    const int lr = tid >> 3;
    const int lc = (tid & 7) << 3;
    const __half* qb = g_qh + (size_t)bh * Ntok * Dd + (size_t)(nt * 64) * Dd;
#pragma unroll
    for (int rr = lr; rr < 64; rr += 32) {
        uint4 qraw = *(const uint4*)(qb + rr * Dd + lc);
        const __half2* qh2 = (const __half2*)&qraw;
#pragma unroll
        for (int j = 0; j < 4; j++) {
            float2 qf = __half22float2(qh2[j]);
            qsT[lc + 2 * j][rr]     = qf.x;
            qsT[lc + 2 * j + 1][rr] = qf.y;
        }
    }
    __syncthreads();

    const int n0 = (tid & 15) << 2, e0 = (tid >> 4) << 2;
    float acc[4][4] = {};
#pragma unroll
    for (int d = 0; d < 64; d++) {
        float4 qa = *(const float4*)&qsT[d][n0];
        float4 kf = *(const float4*)&kvs[d][e0];
        float qr[4] = {qa.x, qa.y, qa.z, qa.w};
        float krr[4] = {kf.x, kf.y, kf.z, kf.w};
#pragma unroll
        for (int i = 0; i < 4; i++)
#pragma unroll
            for (int j = 0; j < 4; j++)
                acc[i][j] = fmaf(qr[i], krr[j], acc[i][j]);
    }

#pragma unroll
    for (int i = 0; i < 4; i++) {
        const int n = nt * 64 + n0 + i;
        const float scale = g_si[bh * Ntok + n] * g_sa[bh * Ntok + n];
        const int np = (h << 9) | (n >> 3);
        const int cbase = (n & 7) << 6;
        const size_t lin = (size_t)(b * Ntok + np) * Cc + cbase + e0;
        __half2 h01 = __floats2half2_rn(acc[i][0] * scale, acc[i][1] * scale);
        __half2 h23 = __floats2half2_rn(acc[i][2] * scale, acc[i][3] * scale);
        *(__half2*)(g_Oh + lin)     = h01;
        *(__half2*)(g_Oh + lin + 2) = h23;
    }
}

// ---------------- launch ----------------
extern "C" void kernel_launch(void* const* d_in, const int* in_sizes, int n_in,
                              void* d_out, int out_size)
{
    const float* query = (const float*)d_in[0];
    const float* Wq = (const float*)d_in[1];
    const float* bq = (const float*)d_in[2];
    const float* Wk = (const float*)d_in[3];
    const float* bk = (const float*)d_in[4];
    const float* Wv = (const float*)d_in[5];
    const float* bv = (const float*)d_in[6];
    const float* Wo = (const float*)d_in[7];
    const float* bo = (const float*)d_in[8];
    const float* temp = (const float*)d_in[9];
    float* out = (float*)d_out;

    const int DSMEM = 3 * 32768 + 1024;
    cudaFuncSetAttribute(gemm_tc, cudaFuncAttributeMaxDynamicSharedMemorySize, DSMEM);

    __half *pAh, *pOh, *pB;
    cudaGetSymbolAddress((void**)&pAh, g_Ah);
    cudaGetSymbolAddress((void**)&pOh, g_Oh);
    cudaGetSymbolAddress((void**)&pB,  g_B);

    // operand conversion
    k_split<<<16384, 256>>>(query, pAh);
    k_convW<<<dim3(16, 16, 4), dim3(32, 8)>>>(Wq, Wk, Wv, Wo, pB);

    // q/k/v projections in one launch (z selects mode/weights)
    gemm_tc<<<dim3(4, 256, 3), 256, DSMEM>>>(pAh, pB, bq, bk, bv, nullptr, nullptr, 0);

    k_colsum<<<dim3(MCH, BH), 256>>>();
    k_fuse1<<<dim3(MCH, BH), 256>>>();
    k_conserved<<<dim3(MCH, BH), 256>>>();
    k_softmax<<<BH, 256>>>(temp);
    k_kv<<<dim3(MCH, BH), 256>>>();
    k_kvred<<<(BH * Dd * Dd + 255) / 256, 256>>>();
    k_outupd<<<dim3(64, BH), 256>>>();

    // output projection (+bias+residual)
    gemm_tc<<<dim3(4, 256, 1), 256, DSMEM>>>(pOh, pB + 3 * (512 * 512), bo, bo, bo,
                                             query, out, 3);
}

// round 7
// speedup vs baseline: 4.8886x; 1.0274x over previous
#include <cuda_runtime.h>
#include <cuda_fp16.h>
#include <math.h>
#include <stdint.h>

#define Ntok 4096
#define Bb   8
#define Cc   512
#define Hh   8
#define Dd   64
#define BH   64          // B*H
#define EPSf 1e-6f
#define NCHUNK 8         // 512 K / 64 per chunk
#define MCH   16         // mid-section chunks

// ---------------- scratch (static device arrays; no allocation) ----------------
__device__ __half g_qh[BH * Ntok * Dd];    // (B,H,N,D) sigmoid(q proj) fp16
__device__ __half g_kh[BH * Ntok * Dd];
__device__ __half g_vh[BH * Ntok * Dd];
__device__ float g_si[BH * Ntok];
__device__ float g_kpart[MCH * BH * Dd],  g_qpart[MCH * BH * Dd];   // plain col sums
__device__ float g_kpart2[MCH * BH * Dd], g_qpart2[MCH * BH * Dd];  // weighted col sums
__device__ float g_esum[MCH * BH];                                   // exp-sum partials
__device__ float g_kv[BH * Dd * Dd];
__device__ float g_kvpart[MCH * BH * Dd * Dd];

// fp16 GEMM operands
__device__ __half g_Ah[32768 * 512];       // fp16(query)
__device__ __half g_Oh[32768 * 512];       // fp16(out_update), scrambled (B,N,C)
__device__ __half g_B[4 * 512 * 512];      // [proj][n][k]

// ---------------- PTX helpers (base-arch only) ----------------
__device__ __forceinline__ uint32_t smem_u32(const void* p) {
    uint32_t a;
    asm("{ .reg .u64 t; cvta.to.shared.u64 t, %1; cvt.u32.u64 %0, t; }" : "=r"(a) : "l"(p));
    return a;
}
__device__ __forceinline__ void cp16(uint32_t dst, const void* src) {
    asm volatile("cp.async.cg.shared.global [%0], [%1], 16;" :: "r"(dst), "l"(src) : "memory");
}
__device__ __forceinline__ void cp_commit() {
    asm volatile("cp.async.commit_group;" ::: "memory");
}
__device__ __forceinline__ void cp_wait2() {
    asm volatile("cp.async.wait_group 2;" ::: "memory");
}
__device__ __forceinline__ void ldm4(uint32_t* r, uint32_t addr) {
    asm volatile("ldmatrix.sync.aligned.m8n8.x4.shared.b16 {%0,%1,%2,%3}, [%4];"
                 : "=r"(r[0]), "=r"(r[1]), "=r"(r[2]), "=r"(r[3]) : "r"(addr));
}
__device__ __forceinline__ void mma16816(float* c, const uint32_t* a, const uint32_t* b) {
    asm volatile(
        "mma.sync.aligned.m16n8k16.row.col.f32.f16.f16.f32 "
        "{%0,%1,%2,%3}, {%4,%5,%6,%7}, {%8,%9}, {%0,%1,%2,%3};"
        : "+f"(c[0]), "+f"(c[1]), "+f"(c[2]), "+f"(c[3])
        : "r"(a[0]), "r"(a[1]), "r"(a[2]), "r"(a[3]), "r"(b[0]), "r"(b[1]));
}

// ---------------- conversion kernels ----------------
__global__ void k_split(const float* __restrict__ src, __half* __restrict__ dst)
{
    int i = blockIdx.x * blockDim.x + threadIdx.x;
    float4 v = ((const float4*)src)[i];
    __half2* hp = (__half2*)dst;
    hp[2 * i]     = __floats2half2_rn(v.x, v.y);
    hp[2 * i + 1] = __floats2half2_rn(v.z, v.w);
}

__global__ void k_convW(const float* __restrict__ Wq, const float* __restrict__ Wk,
                        const float* __restrict__ Wv, const float* __restrict__ Wo,
                        __half* __restrict__ Bop)
{
    const float* W = (blockIdx.z == 0) ? Wq : (blockIdx.z == 1) ? Wk
                   : (blockIdx.z == 2) ? Wv : Wo;
    __half* Bp = Bop + (size_t)blockIdx.z * (512 * 512);
    __shared__ float t[32][33];
    const int k0 = blockIdx.y * 32, n0 = blockIdx.x * 32;
    const int tx = threadIdx.x, ty = threadIdx.y;  // (32,8)
    for (int j = ty; j < 32; j += 8) t[j][tx] = W[(size_t)(k0 + j) * 512 + n0 + tx];
    __syncthreads();
    for (int j = ty; j < 32; j += 8)
        Bp[(size_t)(n0 + j) * 512 + (k0 + tx)] = __float2half_rn(t[tx][j]);
}

// ---------------- mma.sync GEMM: D[32768,512] = A[.,512] @ B^T ----------------
// mode 0: q (sigmoid -> g_qh), 1: k -> g_kh, 2: v -> g_vh, 3: out (+bias+resid -> d_out)
__global__ void __launch_bounds__(256) gemm_tc(
    const __half* __restrict__ A, const __half* __restrict__ Bbase,
    const float* __restrict__ b0, const float* __restrict__ b1, const float* __restrict__ b2,
    const float* __restrict__ resid, float* __restrict__ out, int modeBase)
{
    extern __shared__ char dyn[];
    const uint32_t sbase = (smem_u32(dyn) + 1023u) & ~1023u;
    char* dynA = dyn + (sbase - smem_u32(dyn));   // C++ pointer to aligned base
    const int tid = threadIdx.x;
    const int wid = tid >> 5, lane = tid & 31;
    const int bn = blockIdx.x * 128, bm = blockIdx.y * 128;
    const int mode = modeBase + blockIdx.z;
    const __half* Bop = Bbase + (size_t)blockIdx.z * (512 * 512);
    const float* bias = (mode == 1) ? b1 : (mode == 2) ? b2 : b0;
    const int warpM = wid & 3, warpN = wid >> 2;   // 4 x 2 warps -> 32x64 warp tile

    float acc[2][8][4];
#pragma unroll
    for (int mf = 0; mf < 2; mf++)
#pragma unroll
        for (int nf = 0; nf < 8; nf++)
#pragma unroll
            for (int i = 0; i < 4; i++) acc[mf][nf][i] = 0.f;

    int aRow[2], bRow[4];
#pragma unroll
    for (int mf = 0; mf < 2; mf++)
        aRow[mf] = warpM * 32 + mf * 16 + (lane & 7) + ((lane >> 3) & 1) * 8;
    const int aHi = lane >> 4;
#pragma unroll
    for (int nf2 = 0; nf2 < 4; nf2++)
        bRow[nf2] = warpN * 64 + nf2 * 16 + (lane & 7) + (lane >> 4) * 8;
    const int bHi = (lane >> 3) & 1;

    auto issue = [&](int c) {
        const int akoff = c << 6;
        const uint32_t buf = sbase + (uint32_t)(c % 3) * 32768u;
#pragma unroll
        for (int t = 0; t < 4; t++) {
            int s = tid + (t << 8);
            int row = s >> 3, sc = s & 7;
            uint32_t off = row * 128 + ((sc ^ (row & 7)) << 4);
            cp16(buf + off, A + ((size_t)(bm + row) * 512 + akoff + sc * 8));
        }
#pragma unroll
        for (int t = 0; t < 4; t++) {
            int s = tid + (t << 8);
            int row = s >> 3, sc = s & 7;
            uint32_t off = row * 128 + ((sc ^ (row & 7)) << 4);
            cp16(buf + 16384u + off, Bop + ((size_t)(bn + row) * 512 + akoff + sc * 8));
        }
    };

    issue(0); cp_commit();
    issue(1); cp_commit();

    for (int c = 0; c < NCHUNK; c++) {
        if (c + 2 < NCHUNK) issue(c + 2);
        cp_commit();
        cp_wait2();
        __syncthreads();

        const uint32_t abuf = sbase + (uint32_t)(c % 3) * 32768u;
        const uint32_t bbuf = abuf + 16384u;
#pragma unroll
        for (int ks = 0; ks < 4; ks++) {
            uint32_t a[2][4], b[4][4];
#pragma unroll
            for (int mf = 0; mf < 2; mf++) {
                const int row = aRow[mf];
                const int cc = 2 * ks + aHi;
                ldm4(a[mf], abuf + row * 128 + ((cc ^ (row & 7)) << 4));
            }
#pragma unroll
            for (int nf2 = 0; nf2 < 4; nf2++) {
                const int row = bRow[nf2];
                const int cc = 2 * ks + bHi;
                ldm4(b[nf2], bbuf + row * 128 + ((cc ^ (row & 7)) << 4));
            }
#pragma unroll
            for (int mf = 0; mf < 2; mf++)
#pragma unroll
                for (int nf = 0; nf < 8; nf++)
                    mma16816(acc[mf][nf], a[mf], &b[nf >> 1][(nf & 1) * 2]);
        }
        __syncthreads();
    }

    // ---------------- epilogue ----------------
    if (mode <= 2) {
        __half* smh = (__half*)dynA;
        const int rloc = warpM * 32 + (lane >> 2);
        const int cloc = warpN * 64 + ((lane & 3) << 1);
#pragma unroll
        for (int mf = 0; mf < 2; mf++)
#pragma unroll
            for (int half = 0; half < 2; half++) {
#pragma unroll
                for (int nf = 0; nf < 8; nf++) {
                    const int c0 = bn + cloc + nf * 8;
                    float vx = acc[mf][nf][half * 2 + 0] + bias[c0];
                    float vy = acc[mf][nf][half * 2 + 1] + bias[c0 + 1];
                    if (mode <= 1) {
                        vx = 1.f / (1.f + expf(-vx));
                        vy = 1.f / (1.f + expf(-vy));
                    }
                    *(__half2*)&smh[(rloc + mf * 16 + half * 8) * 136 + cloc + nf * 8]
                        = __floats2half2_rn(vx, vy);
                }
            }
        __syncthreads();
        __half* dstg = (mode == 0) ? g_qh : (mode == 1) ? g_kh : g_vh;
        const int h0 = bn >> 6;
        const int hl = tid >> 7, nl = (tid & 127) >> 3, dp = tid & 7;
#pragma unroll
        for (int bb2 = 0; bb2 < 8; bb2++) {
            uint4 val = *(const uint4*)(smh + (size_t)(nl * 8 + bb2) * 136 + hl * 64 + dp * 8);
            *(uint4*)(dstg + ((size_t)((bb2 << 3) | (h0 + hl)) * Ntok + (bm >> 3) + nl) * Dd + dp * 8) = val;
        }
    } else {
        const int r0base = bm + warpM * 32 + (lane >> 2);
        const int cb = bn + warpN * 64 + ((lane & 3) << 1);
#pragma unroll
        for (int mf = 0; mf < 2; mf++)
#pragma unroll
            for (int half = 0; half < 2; half++) {
                const int r = r0base + mf * 16 + half * 8;
#pragma unroll
                for (int nf = 0; nf < 8; nf++) {
                    const int c0 = cb + nf * 8;
                    const int bb = r >> 12, n = r & 4095;
                    const size_t o = (size_t)((n << 3) | bb) * Cc + c0;
                    float2 rs = *(const float2*)(resid + o);
                    float2 v;
                    v.x = acc[mf][nf][half * 2 + 0] + bias[c0] + rs.x;
                    v.y = acc[mf][nf][half * 2 + 1] + bias[c0 + 1] + rs.y;
                    *(float2*)(out + o) = v;
                }
            }
    }
}

// ---------------- plain column sums over s (fp16 inputs, fp32 accum) ----------------
__global__ void k_colsum()
{
    const int bh = blockIdx.y, chunk = blockIdx.x;
    const int dp = threadIdx.x & 31, p = threadIdx.x >> 5;
    const __half* kb = g_kh + (size_t)bh * Ntok * Dd;
    const __half* qb = g_qh + (size_t)bh * Ntok * Dd;
    float ak0 = 0.f, ak1 = 0.f, aq0 = 0.f, aq1 = 0.f;
    const int s0 = chunk * 256;
    for (int s = s0 + p; s < s0 + 256; s += 8) {
        float2 kf = __half22float2(*(const __half2*)(kb + (size_t)s * Dd + 2 * dp));
        float2 qf = __half22float2(*(const __half2*)(qb + (size_t)s * Dd + 2 * dp));
        ak0 += kf.x; ak1 += kf.y;
        aq0 += qf.x; aq1 += qf.y;
    }
    __shared__ float sk[8][64], sq[8][64];
    sk[p][2 * dp] = ak0; sk[p][2 * dp + 1] = ak1;
    sq[p][2 * dp] = aq0; sq[p][2 * dp + 1] = aq1;
    __syncthreads();
    if (threadIdx.x < 64) {
        const int d = threadIdx.x;
        float a = 0.f, b = 0.f;
#pragma unroll
        for (int i = 0; i < 8; i++) { a += sk[i][d]; b += sq[i][d]; }
        g_kpart[(chunk * BH + bh) * Dd + d] = a;
        g_qpart[(chunk * BH + bh) * Dd + d] = b;
    }
}

// ---------------- fused: reduce colsum partials + rownorm (si/so) + weighted colsums ----------------
__global__ void __launch_bounds__(256) k_fuse1()
{
    const int bh = blockIdx.y, chunk = blockIdx.x;
    const int w = threadIdx.x >> 5, lane = threadIdx.x & 31;
    __shared__ float ksS[64], qsS[64];
    __shared__ float sQ[8][64], sK[8][64];
    if (threadIdx.x < 64) {
        float a = 0.f, b = 0.f;
#pragma unroll
        for (int c = 0; c < MCH; c++) {
            a += g_kpart[(c * BH + bh) * Dd + threadIdx.x];
            b += g_qpart[(c * BH + bh) * Dd + threadIdx.x];
        }
        ksS[threadIdx.x] = a + EPSf;
        qsS[threadIdx.x] = b + EPSf;
    }
    __syncthreads();
    const __half* qb = g_qh + (size_t)bh * Ntok * Dd;
    const __half* kb = g_kh + (size_t)bh * Ntok * Dd;
    const float ks0 = ksS[2 * lane], ks1 = ksS[2 * lane + 1];
    const float qs0 = qsS[2 * lane], qs1 = qsS[2 * lane + 1];
    float aq0 = 0.f, aq1 = 0.f, ak0 = 0.f, ak1 = 0.f;
    const int s0 = chunk * 256 + w * 32;
    for (int i = 0; i < 32; i++) {
        const int s = s0 + i;
        float2 qf = __half22float2(*(const __half2*)(qb + (size_t)s * Dd + 2 * lane));
        float2 kf = __half22float2(*(const __half2*)(kb + (size_t)s * Dd + 2 * lane));
        float s1 = (qf.x + EPSf) * ks0 + (qf.y + EPSf) * ks1;
        float s2 = (kf.x + EPSf) * qs0 + (kf.y + EPSf) * qs1;
#pragma unroll
        for (int o = 16; o > 0; o >>= 1) {
            s1 += __shfl_xor_sync(0xffffffffu, s1, o);
            s2 += __shfl_xor_sync(0xffffffffu, s2, o);
        }
        const float si = 1.f / (s1 + EPSf);
        const float so = 1.f / (s2 + EPSf);
        if (lane == 0) g_si[bh * Ntok + s] = si;
        aq0 += si * qf.x; aq1 += si * qf.y;
        ak0 += so * kf.x; ak1 += so * kf.y;
    }
    sQ[w][2 * lane] = aq0; sQ[w][2 * lane + 1] = aq1;
    sK[w][2 * lane] = ak0; sK[w][2 * lane + 1] = ak1;
    __syncthreads();
    if (threadIdx.x < 64) {
        const int d = threadIdx.x;
        float sq = 0.f, sk = 0.f;
#pragma unroll
        for (int w2 = 0; w2 < 8; w2++) { sq += sQ[w2][d]; sk += sK[w2][d]; }
        g_qpart2[(chunk * BH + bh) * Dd + d] = sq;   // si-weighted q sums -> qsi
        g_kpart2[(chunk * BH + bh) * Dd + d] = sk;   // so-weighted k sums -> kso
    }
}

// ---------------- fused: conserved_source (inline) + exp + kv partials + exp-sum ----------------
__global__ void __launch_bounds__(256) k_kv(const float* __restrict__ tptr)
{
    const int bh = blockIdx.y, chunk = blockIdx.x;
    __shared__ float ks[32][64];
    __shared__ float ws[32][64];
    __shared__ float qsiS[64];
    __shared__ float esred[32];
    const int tid = threadIdx.x;
    const int lr = tid >> 3;
    const int lc = (tid & 7) << 3;
    if (tid < 64) {
        float a = 0.f;
#pragma unroll
        for (int c = 0; c < MCH; c++) a += g_qpart2[(c * BH + bh) * Dd + tid];
        qsiS[tid] = a + EPSf;           // qsi + eps
    }
    __syncthreads();
    const float invT = 1.f / tptr[0];
    const size_t base = (size_t)bh * Ntok * Dd;
    const int d0 = (tid & 15) << 2, e0 = (tid >> 4) << 2;
    float acc[4][4] = {};
    float esum = 0.f;
    for (int s0 = chunk * 256; s0 < chunk * 256 + 256; s0 += 32) {
        const int s = s0 + lr;
        uint4 kraw = *(const uint4*)(g_kh + base + (size_t)s * Dd + lc);
        uint4 vraw = *(const uint4*)(g_vh + base + (size_t)s * Dd + lc);
        const __half2* kh2 = (const __half2*)&kraw;
        const __half2* vh2 = (const __half2*)&vraw;
        float kvals[8], vvals[8];
        float pd = 0.f;
#pragma unroll
        for (int j = 0; j < 4; j++) {
            float2 kf = __half22float2(kh2[j]);
            float2 vf = __half22float2(vh2[j]);
            kvals[2 * j] = kf.x; kvals[2 * j + 1] = kf.y;
            vvals[2 * j] = vf.x; vvals[2 * j + 1] = vf.y;
            pd += (kf.x + EPSf) * qsiS[lc + 2 * j] + (kf.y + EPSf) * qsiS[lc + 2 * j + 1];
        }
        // reduce dot across the 8 threads of this row
        pd += __shfl_xor_sync(0xffffffffu, pd, 1);
        pd += __shfl_xor_sync(0xffffffffu, pd, 2);
        pd += __shfl_xor_sync(0xffffffffu, pd, 4);
        const float cs = fminf(1.f, fmaxf(-1.f, pd + EPSf));
        const float e = expf(cs * invT);
        if ((tid & 7) == 0) esum += e;
#pragma unroll
        for (int j = 0; j < 8; j++) {
            ks[lr][lc + j] = kvals[j];
            ws[lr][lc + j] = vvals[j] * e;
        }
        __syncthreads();
#pragma unroll
        for (int ss = 0; ss < 32; ss++) {
            float4 kf = *(const float4*)&ks[ss][d0];
            float4 wf = *(const float4*)&ws[ss][e0];
            float krr[4] = {kf.x, kf.y, kf.z, kf.w};
            float wr[4] = {wf.x, wf.y, wf.z, wf.w};
#pragma unroll
            for (int i = 0; i < 4; i++)
#pragma unroll
                for (int j = 0; j < 4; j++)
                    acc[i][j] = fmaf(krr[i], wr[j], acc[i][j]);
        }
        __syncthreads();
    }
    if ((tid & 7) == 0) esred[tid >> 3] = esum;
    __syncthreads();
    if (tid == 0) {
        float t = 0.f;
#pragma unroll
        for (int i = 0; i < 32; i++) t += esred[i];
        g_esum[chunk * BH + bh] = t;
    }
    float* dst = g_kvpart + ((size_t)chunk * BH + bh) * Dd * Dd;
#pragma unroll
    for (int i = 0; i < 4; i++)
#pragma unroll
        for (int j = 0; j < 4; j++)
            dst[(d0 + i) * Dd + e0 + j] = acc[i][j];
}

// ---------------- reduce kv partials, apply softmax scale C/Σe ----------------
__global__ void k_kvred()
{
    const int i = blockIdx.x * blockDim.x + threadIdx.x;
    if (i >= BH * Dd * Dd) return;
    const int bh = i >> 12;
    float es = 0.f;
#pragma unroll
    for (int c = 0; c < MCH; c++) es += g_esum[c * BH + bh];
    const float scale = (float)Cc / es;
    float s = 0.f;
#pragma unroll
    for (int c = 0; c < MCH; c++) s += g_kvpart[(size_t)c * BH * Dd * Dd + i];
    g_kv[i] = s * scale;
}

// ---------------- out_update = (q @ kv) * si * sigmoid(q·(kso+eps)+eps) -> fp16 ----------------
__global__ void __launch_bounds__(256) k_outupd()
{
    const int bh = blockIdx.y, nt = blockIdx.x;
    const int b = bh >> 3, h = bh & 7;
    __shared__ float kvs[64][64];
    __shared__ float qsT[64][68];
    __shared__ float ksoS[64];
    const int tid = threadIdx.x;

    if (tid < 64) {
        float a = 0.f;
#pragma unroll
        for (int c = 0; c < MCH; c++) a += g_kpart2[(c * BH + bh) * Dd + tid];
        ksoS[tid] = a + EPSf;           // kso + eps
    }

    const float4* kvsrc = (const float4*)(g_kv + (size_t)bh * (Dd * Dd));
    for (int i = tid; i < 1024; i += 256) ((float4*)kvs)[i] = kvsrc[i];

    const int lr = tid >> 3;
    const int lc = (tid & 7) << 3;
    const __half* qb = g_qh + (size_t)bh * Ntok * Dd + (size_t)(nt * 64) * Dd;
#pragma unroll
    for (int rr = lr; rr < 64; rr += 32) {
        uint4 qraw = *(const uint4*)(qb + rr * Dd + lc);
        const __half2* qh2 = (const __half2*)&qraw;
#pragma unroll
        for (int j = 0; j < 4; j++) {
            float2 qf = __half22float2(qh2[j]);
            qsT[lc + 2 * j][rr]     = qf.x;
            qsT[lc + 2 * j + 1][rr] = qf.y;
        }
    }
    __syncthreads();

    float ksoSum = 0.f;
#pragma unroll
    for (int d = 0; d < 64; d++) ksoSum += ksoS[d];

    const int n0 = (tid & 15) << 2, e0 = (tid >> 4) << 2;
    float acc[4][4] = {};
    float sadot[4] = {};
#pragma unroll
    for (int d = 0; d < 64; d++) {
        float4 qa = *(const float4*)&qsT[d][n0];
        float4 kf = *(const float4*)&kvs[d][e0];
        const float ko = ksoS[d];
        float qr[4] = {qa.x, qa.y, qa.z, qa.w};
        float krr[4] = {kf.x, kf.y, kf.z, kf.w};
#pragma unroll
        for (int i = 0; i < 4; i++) {
            sadot[i] = fmaf(qr[i], ko, sadot[i]);
#pragma unroll
            for (int j = 0; j < 4; j++)
                acc[i][j] = fmaf(qr[i], krr[j], acc[i][j]);
        }
    }

#pragma unroll
    for (int i = 0; i < 4; i++) {
        const int n = nt * 64 + n0 + i;
        const float cs_sink = sadot[i] + EPSf * ksoSum + EPSf;
        const float sa = 1.f / (1.f + expf(-cs_sink));
        const float scale = g_si[bh * Ntok + n] * sa;
        const int np = (h << 9) | (n >> 3);
        const int cbase = (n & 7) << 6;
        const size_t lin = (size_t)(b * Ntok + np) * Cc + cbase + e0;
        __half2 h01 = __floats2half2_rn(acc[i][0] * scale, acc[i][1] * scale);
        __half2 h23 = __floats2half2_rn(acc[i][2] * scale, acc[i][3] * scale);
        *(__half2*)(g_Oh + lin)     = h01;
        *(__half2*)(g_Oh + lin + 2) = h23;
    }
}

// ---------------- launch ----------------
extern "C" void kernel_launch(void* const* d_in, const int* in_sizes, int n_in,
                              void* d_out, int out_size)
{
    const float* query = (const float*)d_in[0];
    const float* Wq = (const float*)d_in[1];
    const float* bq = (const float*)d_in[2];
    const float* Wk = (const float*)d_in[3];
    const float* bk = (const float*)d_in[4];
    const float* Wv = (const float*)d_in[5];
    const float* bv = (const float*)d_in[6];
    const float* Wo = (const float*)d_in[7];
    const float* bo = (const float*)d_in[8];
    const float* temp = (const float*)d_in[9];
    float* out = (float*)d_out;

    const int DSMEM = 3 * 32768 + 1024;
    cudaFuncSetAttribute(gemm_tc, cudaFuncAttributeMaxDynamicSharedMemorySize, DSMEM);

    __half *pAh, *pOh, *pB;
    cudaGetSymbolAddress((void**)&pAh, g_Ah);
    cudaGetSymbolAddress((void**)&pOh, g_Oh);
    cudaGetSymbolAddress((void**)&pB,  g_B);

    // operand conversion
    k_split<<<16384, 256>>>(query, pAh);
    k_convW<<<dim3(16, 16, 4), dim3(32, 8)>>>(Wq, Wk, Wv, Wo, pB);

    // q/k/v projections in one launch (z selects mode/weights)
    gemm_tc<<<dim3(4, 256, 3), 256, DSMEM>>>(pAh, pB, bq, bk, bv, nullptr, nullptr, 0);

    k_colsum<<<dim3(MCH, BH), 256>>>();
    k_fuse1<<<dim3(MCH, BH), 256>>>();
    k_kv<<<dim3(MCH, BH), 256>>>(temp);
    k_kvred<<<(BH * Dd * Dd + 255) / 256, 256>>>();
    k_outupd<<<dim3(64, BH), 256>>>();

    // output projection (+bias+residual)
    gemm_tc<<<dim3(4, 256, 1), 256, DSMEM>>>(pOh, pB + 3 * (512 * 512), bo, bo, bo,
                                             query, out, 3);
}